// round 12
// baseline (speedup 1.0000x reference)
#include <cuda_runtime.h>
#include <cuda_bf16.h>
#include <math.h>
#include <stdint.h>

#define S_LEN 1024
#define BATCH 8
#define DMODEL 768
#define NHEAD 12
#define HDIM 64
#define PROMPT_NUM 8
#define TOKENS (S_LEN - PROMPT_NUM)           // 1016
#define MROWS (S_LEN * BATCH)                 // 8192
#define SBD ((size_t)S_LEN * BATCH * DMODEL)  // 6291456
#define AST 68                                // attention smem row stride
#define GK DMODEL                             // K of both GEMMs = 768

// ---------------- bf16 split scratch (allocation-free rule) ----------------
__device__ __nv_bfloat16 g_xh[(size_t)MROWS * GK];
__device__ __nv_bfloat16 g_xl[(size_t)MROWS * GK];
__device__ __nv_bfloat16 g_wih[(size_t)3 * DMODEL * GK];
__device__ __nv_bfloat16 g_wil[(size_t)3 * DMODEL * GK];
__device__ __nv_bfloat16 g_woh[(size_t)DMODEL * GK];
__device__ __nv_bfloat16 g_wol[(size_t)DMODEL * GK];
__device__ __nv_bfloat16 g_mixh[(size_t)MROWS * DMODEL];
__device__ __nv_bfloat16 g_mixl[(size_t)MROWS * DMODEL];

// ---------------- PTX helpers (sm_80-class only: no tcgen05) ----------------
__device__ __forceinline__ uint32_t smem_u32(const void* p) {
    uint32_t a;
    asm("{ .reg .u64 t; cvta.to.shared.u64 t, %1; cvt.u32.u64 %0, t; }" : "=r"(a) : "l"(p));
    return a;
}

#define CP_ASYNC16(dst, src) \
    asm volatile("cp.async.cg.shared.global [%0], [%1], 16;" :: "r"(dst), "l"(src) : "memory")
#define CP_COMMIT() asm volatile("cp.async.commit_group;" ::: "memory")
#define CP_WAIT0() asm volatile("cp.async.wait_group 0;" ::: "memory")
#define CP_WAIT1() asm volatile("cp.async.wait_group 1;" ::: "memory")

__device__ __forceinline__ void ldmx4(uint32_t* r, uint32_t addr) {
    asm volatile("ldmatrix.sync.aligned.m8n8.x4.shared.b16 {%0,%1,%2,%3}, [%4];"
                 : "=r"(r[0]), "=r"(r[1]), "=r"(r[2]), "=r"(r[3]) : "r"(addr));
}
// NON-transposed x2: B tiles are stored [n][k] (k contiguous), which IS the
// col-major B layout mma.row.col expects.
__device__ __forceinline__ void ldmx2(uint32_t* r, uint32_t addr) {
    asm volatile("ldmatrix.sync.aligned.m8n8.x2.shared.b16 {%0,%1}, [%2];"
                 : "=r"(r[0]), "=r"(r[1]) : "r"(addr));
}
__device__ __forceinline__ void mma_bf16(float* c, const uint32_t* a, const uint32_t* b) {
    asm volatile(
        "mma.sync.aligned.m16n8k16.row.col.f32.bf16.bf16.f32 "
        "{%0,%1,%2,%3}, {%4,%5,%6,%7}, {%8,%9}, {%0,%1,%2,%3};"
        : "+f"(c[0]), "+f"(c[1]), "+f"(c[2]), "+f"(c[3])
        : "r"(a[0]), "r"(a[1]), "r"(a[2]), "r"(a[3]), "r"(b[0]), "r"(b[1]));
}

// smem tile geometry: [128 rows][40 bf16] (32 data + 8 pad) = 80 B/row, 10240 B/array
#define TROW 80
#define TBYTES 10240
#define STAGE (4 * TBYTES)   // Ah, Al, Bh, Bl per stage = 40960

// ---------------- fp32 -> bf16 hi/lo split ----------------
__global__ __launch_bounds__(256) void convert_split_kernel(
    const float* __restrict__ in, __nv_bfloat16* __restrict__ hi,
    __nv_bfloat16* __restrict__ lo, int n4)
{
    int i = blockIdx.x * blockDim.x + threadIdx.x;
    if (i >= n4) return;
    float4 v = ((const float4*)in)[i];
    __nv_bfloat16 h0 = __float2bfloat16(v.x);
    __nv_bfloat16 h1 = __float2bfloat16(v.y);
    __nv_bfloat16 h2 = __float2bfloat16(v.z);
    __nv_bfloat16 h3 = __float2bfloat16(v.w);
    __nv_bfloat16 l0 = __float2bfloat16(v.x - __bfloat162float(h0));
    __nv_bfloat16 l1 = __float2bfloat16(v.y - __bfloat162float(h1));
    __nv_bfloat16 l2 = __float2bfloat16(v.z - __bfloat162float(h2));
    __nv_bfloat16 l3 = __float2bfloat16(v.w - __bfloat162float(h3));
    __nv_bfloat162* H = (__nv_bfloat162*)hi;
    __nv_bfloat162* L = (__nv_bfloat162*)lo;
    H[2 * i]     = __nv_bfloat162(h0, h1);
    H[2 * i + 1] = __nv_bfloat162(h2, h3);
    L[2 * i]     = __nv_bfloat162(l0, l1);
    L[2 * i + 1] = __nv_bfloat162(l2, l3);
}

// ----------------------------------------------------------------------------
// mma.sync bf16 GEMM: C[r,n] = sum_k (Ah+Al)[r,k]*(Bh+Bl)[n,k] + bias[n]
// 3-term split: Ah*Bh + Ah*Bl + Al*Bh. 128x128 CTA tile, 8 warps (2m x 4n),
// warp tile 64x32 = 4x4 m16n8k16. BK=32, double-buffered cp.async.
// __launch_bounds__(256, 2): cap regs at 128 so TWO CTAs are resident per SM
// (R11 ran 1 CTA at 152 regs -> tensor pipe 50% idle during barriers/loads).
// Column n scattered to region n/768 at region_stride (QKV q/k/v split).
// ----------------------------------------------------------------------------
__global__ __launch_bounds__(256, 2) void mma_gemm_kernel(
    const __nv_bfloat16* __restrict__ Ah_, const __nv_bfloat16* __restrict__ Al_,
    const __nv_bfloat16* __restrict__ Bh_, const __nv_bfloat16* __restrict__ Bl_,
    const float* __restrict__ bias, float* __restrict__ C, size_t region_stride)
{
    extern __shared__ char smem[];
    const uint32_t sb = smem_u32(smem);
    const int tid = threadIdx.x;
    const int wid = tid >> 5;
    const int lane = tid & 31;
    const int wm = wid & 1;          // warp row (0..1) -> 64 rows
    const int wn = wid >> 1;         // warp col (0..3) -> 32 cols
    const int row0 = blockIdx.y * 128;
    const int col0 = blockIdx.x * 128;

    const char* gA_h = (const char*)(Ah_ + (size_t)row0 * GK);
    const char* gA_l = (const char*)(Al_ + (size_t)row0 * GK);
    const char* gB_h = (const char*)(Bh_ + (size_t)col0 * GK);
    const char* gB_l = (const char*)(Bl_ + (size_t)col0 * GK);

    // per-thread cp.async assignment: 2 granules per array
    const int r0g = (tid + 0)   >> 2, g0 = (tid + 0)   & 3;
    const int r1g = (tid + 256) >> 2, g1 = (tid + 256) & 3;

#define LOAD_CHUNK(kc, stage) do {                                          \
        const uint32_t s0_ = sb + (stage) * STAGE;                          \
        {                                                                   \
            uint32_t d = (uint32_t)r0g * TROW + g0 * 16;                    \
            size_t src = (size_t)r0g * (GK * 2) + (size_t)(kc) * 64 + g0 * 16; \
            CP_ASYNC16(s0_ + 0 * TBYTES + d, gA_h + src);                   \
            CP_ASYNC16(s0_ + 1 * TBYTES + d, gA_l + src);                   \
            CP_ASYNC16(s0_ + 2 * TBYTES + d, gB_h + src);                   \
            CP_ASYNC16(s0_ + 3 * TBYTES + d, gB_l + src);                   \
        }                                                                   \
        {                                                                   \
            uint32_t d = (uint32_t)r1g * TROW + g1 * 16;                    \
            size_t src = (size_t)r1g * (GK * 2) + (size_t)(kc) * 64 + g1 * 16; \
            CP_ASYNC16(s0_ + 0 * TBYTES + d, gA_h + src);                   \
            CP_ASYNC16(s0_ + 1 * TBYTES + d, gA_l + src);                   \
            CP_ASYNC16(s0_ + 2 * TBYTES + d, gB_h + src);                   \
            CP_ASYNC16(s0_ + 3 * TBYTES + d, gB_l + src);                   \
        }                                                                   \
        CP_COMMIT();                                                        \
    } while (0)

    float acc[4][4][4];
#pragma unroll
    for (int im = 0; im < 4; im++)
#pragma unroll
        for (int jn = 0; jn < 4; jn++)
#pragma unroll
            for (int q = 0; q < 4; q++) acc[im][jn][q] = 0.0f;

    // ldmatrix per-lane byte offsets within an array
    // A (x4): row = wm*64 + im*16 + (lane&7) + ((lane>>3)&1)*8, kcol = (lane>>4)*8
    const uint32_t aoff = (uint32_t)(wm * 64 + (lane & 7) + ((lane >> 3) & 1) * 8) * TROW
                        + (uint32_t)(lane >> 4) * 16;
    // B (x2, non-trans): lanes 0-7 -> n-rows (k0-7 piece), lanes 8-15 -> same
    // n-rows at +16B (k8-15 piece)
    const int l15 = lane & 15;
    const uint32_t boff = (uint32_t)(wn * 32 + (l15 & 7)) * TROW
                        + (uint32_t)((l15 >> 3) & 1) * 16;

    LOAD_CHUNK(0, 0);
    const int NKC = GK / 32;  // 24
    for (int kc = 0; kc < NKC; kc++) {
        if (kc + 1 < NKC) { LOAD_CHUNK(kc + 1, (kc + 1) & 1); CP_WAIT1(); }
        else              { CP_WAIT0(); }
        __syncthreads();

        const uint32_t s0 = sb + (kc & 1) * STAGE;
#pragma unroll
        for (int k16 = 0; k16 < 2; k16++) {
            const uint32_t kb = (uint32_t)k16 * 32;  // 16 cols * 2B
            uint32_t bh[4][2], bl[4][2];
#pragma unroll
            for (int jn = 0; jn < 4; jn++) {
                ldmx2(bh[jn], s0 + 2 * TBYTES + boff + jn * 8 * TROW + kb);
                ldmx2(bl[jn], s0 + 3 * TBYTES + boff + jn * 8 * TROW + kb);
            }
#pragma unroll
            for (int im = 0; im < 4; im++) {
                uint32_t ah[4], al[4];
                ldmx4(ah, s0 + 0 * TBYTES + aoff + im * 16 * TROW + kb);
                ldmx4(al, s0 + 1 * TBYTES + aoff + im * 16 * TROW + kb);
#pragma unroll
                for (int jn = 0; jn < 4; jn++) {
                    mma_bf16(acc[im][jn], ah, bh[jn]);
                    mma_bf16(acc[im][jn], ah, bl[jn]);
                    mma_bf16(acc[im][jn], al, bh[jn]);
                }
            }
        }
        __syncthreads();  // WAR guard: next iter's cp.async overwrites this buffer
    }

    // epilogue: direct register -> global stores with bias + region scatter
    const int gid = lane >> 2, tq = lane & 3;
#pragma unroll
    for (int jn = 0; jn < 4; jn++) {
        const int colg = col0 + wn * 32 + jn * 8 + tq * 2;
        const int region = colg / DMODEL;
        const int cc = colg - region * DMODEL;
        float* Cb = C + (size_t)region * region_stride + cc;
        const float bx = bias[colg], by = bias[colg + 1];
#pragma unroll
        for (int im = 0; im < 4; im++) {
            const int rg = row0 + wm * 64 + im * 16 + gid;
            float2 v0, v1;
            v0.x = acc[im][jn][0] + bx; v0.y = acc[im][jn][1] + by;
            v1.x = acc[im][jn][2] + bx; v1.y = acc[im][jn][3] + by;
            *(float2*)(Cb + (size_t)rg * DMODEL) = v0;
            *(float2*)(Cb + (size_t)(rg + 8) * DMODEL) = v1;
        }
    }
#undef LOAD_CHUNK
}

// ----------------------------------------------------------------------------
// Flash attention: 128 q-rows per block, 256 threads, shfl-only softmax,
// 3 syncs per 64-key tile. NEW in R12: K/V tiles are prefetched into
// registers for the NEXT tile right after the current tiles-ready barrier,
// hiding the ~600-cycle global-load latency behind score/softmax/PV compute.
// Epilogue emits mix as bf16 hi/lo for the mma.sync out-projection.
// ----------------------------------------------------------------------------
__global__ __launch_bounds__(256, 2) void attn_kernel(
    const float* __restrict__ qg, const float* __restrict__ kg,
    const float* __restrict__ vg,
    __nv_bfloat16* __restrict__ mixh, __nv_bfloat16* __restrict__ mixl)
{
    extern __shared__ float sm[];
    float* Qs = sm;                    // [128][AST]
    float* Ks = Qs + 128 * AST;        // [64][AST]
    float* Vt = Ks + 64 * AST;         // [64][AST]  dh-major (transposed)
    float* Ps = Vt + 64 * AST;         // [128][AST]

    const int tid = threadIdx.x;
    const int tx = tid & 15;
    const int ty = tid >> 4;
    const int bh = blockIdx.y;
    const int b = bh / NHEAD;
    const int h = bh - b * NHEAD;
    const int q0 = blockIdx.x * 128;
    const size_t rstride = (size_t)BATCH * DMODEL;

    const float* qbase = qg + (size_t)q0 * rstride + (size_t)b * DMODEL + h * HDIM;
    const float* kbase = kg + (size_t)b * DMODEL + h * HDIM;
    const float* vbase = vg + (size_t)b * DMODEL + h * HDIM;

    // loader lane mapping: row rr+16i, column quad c4 (constant across i)
    const int rr = tid >> 4;          // 0..15
    const int c4 = (tid & 15) * 4;    // 0..60

    // load Q tile (128 x 64)
#pragma unroll
    for (int i = 0; i < 8; i++) {
        int r = rr + i * 16;
        *(float4*)(Qs + r * AST + c4) = *(const float4*)(qbase + (size_t)r * rstride + c4);
    }

    float4 kreg[4], vreg[4];
#pragma unroll
    for (int i = 0; i < 4; i++) {
        const size_t off = (size_t)(rr + i * 16) * rstride + c4;
        kreg[i] = *(const float4*)(kbase + off);
        vreg[i] = *(const float4*)(vbase + off);
    }

    float mrow[8], lrow[8], acc[8][4];
    bool qm[8];
#pragma unroll
    for (int i = 0; i < 8; i++) {
        mrow[i] = -1e30f; lrow[i] = 0.0f;
        int qr = q0 + ty * 8 + i;
        qm[i] = (qr == 0) || (qr >= TOKENS);
#pragma unroll
        for (int j = 0; j < 4; j++) acc[i][j] = 0.0f;
    }

    for (int kt = 0; kt < S_LEN; kt += 64) {
        // commit prefetched regs to smem
#pragma unroll
        for (int i = 0; i < 4; i++) {
            const int r = rr + i * 16;
            *(float4*)(Ks + r * AST + c4) = kreg[i];
            Vt[(c4 + 0) * AST + r] = vreg[i].x;
            Vt[(c4 + 1) * AST + r] = vreg[i].y;
            Vt[(c4 + 2) * AST + r] = vreg[i].z;
            Vt[(c4 + 3) * AST + r] = vreg[i].w;
        }
        __syncthreads();  // (1) tiles ready (covers Qs on first iter)

        // prefetch next tile into regs — overlaps with all compute below
        if (kt + 64 < S_LEN) {
#pragma unroll
            for (int i = 0; i < 4; i++) {
                const size_t off = (size_t)(kt + 64 + rr + i * 16) * rstride + c4;
                kreg[i] = *(const float4*)(kbase + off);
                vreg[i] = *(const float4*)(vbase + off);
            }
        }

        // scores s[i][j] = Q[row] . K[col]
        float s[8][4];
#pragma unroll
        for (int i = 0; i < 8; i++)
#pragma unroll
            for (int j = 0; j < 4; j++) s[i][j] = 0.0f;

#pragma unroll
        for (int kk = 0; kk < HDIM; kk += 4) {
            float4 kf[4];
#pragma unroll
            for (int j = 0; j < 4; j++)
                kf[j] = *(const float4*)(Ks + (tx + j * 16) * AST + kk);
#pragma unroll
            for (int i = 0; i < 8; i++) {
                float4 qf = *(const float4*)(Qs + (ty * 8 + i) * AST + kk);
#pragma unroll
                for (int j = 0; j < 4; j++) {
                    s[i][j] = fmaf(qf.x, kf[j].x, s[i][j]);
                    s[i][j] = fmaf(qf.y, kf[j].y, s[i][j]);
                    s[i][j] = fmaf(qf.z, kf[j].z, s[i][j]);
                    s[i][j] = fmaf(qf.w, kf[j].w, s[i][j]);
                }
            }
        }

        // scale + mask + per-row max (replicated over 16-lane groups)
        bool kmask[4];
#pragma unroll
        for (int j = 0; j < 4; j++) kmask[j] = (kt + tx + j * 16) >= TOKENS;

        float tm[8];
#pragma unroll
        for (int i = 0; i < 8; i++) {
            float m = -1e30f;
#pragma unroll
            for (int j = 0; j < 4; j++) {
                float v = s[i][j] * 0.125f;
                if (kmask[j] && qm[i]) v = -10000.0f;
                s[i][j] = v;
                m = fmaxf(m, v);
            }
            tm[i] = m;
        }
#pragma unroll
        for (int o = 1; o < 16; o <<= 1)
#pragma unroll
            for (int i = 0; i < 8; i++)
                tm[i] = fmaxf(tm[i], __shfl_xor_sync(0xffffffffu, tm[i], o));

        float psum[8];
#pragma unroll
        for (int i = 0; i < 8; i++) {
            float nm = fmaxf(mrow[i], tm[i]);
            float f = __expf(mrow[i] - nm);
            mrow[i] = nm;
            lrow[i] *= f;
#pragma unroll
            for (int j = 0; j < 4; j++) acc[i][j] *= f;
            float ps = 0.0f;
#pragma unroll
            for (int j = 0; j < 4; j++) {
                float p = __expf(s[i][j] - nm);
                Ps[(ty * 8 + i) * AST + tx + j * 16] = p;
                ps += p;
            }
            psum[i] = ps;
        }
#pragma unroll
        for (int o = 1; o < 16; o <<= 1)
#pragma unroll
            for (int i = 0; i < 8; i++)
                psum[i] += __shfl_xor_sync(0xffffffffu, psum[i], o);
#pragma unroll
        for (int i = 0; i < 8; i++) lrow[i] += psum[i];
        __syncthreads();  // (2) Ps written

        // O += P * V
#pragma unroll
        for (int kk = 0; kk < 64; kk += 4) {
            float4 vf[4];
#pragma unroll
            for (int j = 0; j < 4; j++)
                vf[j] = *(const float4*)(Vt + (tx + j * 16) * AST + kk);
#pragma unroll
            for (int i = 0; i < 8; i++) {
                float4 pf = *(const float4*)(Ps + (ty * 8 + i) * AST + kk);
#pragma unroll
                for (int j = 0; j < 4; j++) {
                    acc[i][j] = fmaf(pf.x, vf[j].x, acc[i][j]);
                    acc[i][j] = fmaf(pf.y, vf[j].y, acc[i][j]);
                    acc[i][j] = fmaf(pf.z, vf[j].z, acc[i][j]);
                    acc[i][j] = fmaf(pf.w, vf[j].w, acc[i][j]);
                }
            }
        }
        __syncthreads();  // (3) smem consumed; next iter may overwrite
    }

    // epilogue: normalize, split to bf16 hi/lo
#pragma unroll
    for (int i = 0; i < 8; i++) {
        int qr = q0 + ty * 8 + i;
        float inv = 1.0f / lrow[i];
        size_t base = ((size_t)qr * BATCH + b) * DMODEL + h * HDIM;
#pragma unroll
        for (int j = 0; j < 4; j++) {
            float o = acc[i][j] * inv;
            __nv_bfloat16 hh = __float2bfloat16(o);
            __nv_bfloat16 ll = __float2bfloat16(o - __bfloat162float(hh));
            mixh[base + tx + j * 16] = hh;
            mixl[base + tx + j * 16] = ll;
        }
    }
}

extern "C" void kernel_launch(void* const* d_in, const int* in_sizes, int n_in,
                              void* d_out, int out_size)
{
    const float* x      = (const float*)d_in[0];  // (S, B, D)
    const float* w_in   = (const float*)d_in[1];  // (3D, D)
    const float* b_in   = (const float*)d_in[2];  // (3D,)
    const float* w_out  = (const float*)d_in[3];  // (D, D)
    const float* b_out  = (const float*)d_in[4];  // (D,)
    float* out = (float*)d_out;

    float* q_out = out;            // q/k/v regions: [r=s*B+b][d]
    float* o_out = out + 3 * SBD;  // (S, B, D)

    __nv_bfloat16 *xh, *xl, *wih, *wil, *woh, *wol, *mixh, *mixl;
    cudaGetSymbolAddress((void**)&xh,   g_xh);
    cudaGetSymbolAddress((void**)&xl,   g_xl);
    cudaGetSymbolAddress((void**)&wih,  g_wih);
    cudaGetSymbolAddress((void**)&wil,  g_wil);
    cudaGetSymbolAddress((void**)&woh,  g_woh);
    cudaGetSymbolAddress((void**)&wol,  g_wol);
    cudaGetSymbolAddress((void**)&mixh, g_mixh);
    cudaGetSymbolAddress((void**)&mixl, g_mixl);

    const int gemm_smem = 2 * STAGE;  // 81920
    cudaFuncSetAttribute(mma_gemm_kernel, cudaFuncAttributeMaxDynamicSharedMemorySize, gemm_smem);

    // 0) fp32 -> bf16 hi/lo splits
    convert_split_kernel<<<(MROWS * GK / 4 + 255) / 256, 256>>>(x, xh, xl, MROWS * GK / 4);
    convert_split_kernel<<<(3 * DMODEL * GK / 4 + 255) / 256, 256>>>(w_in, wih, wil, 3 * DMODEL * GK / 4);
    convert_split_kernel<<<(DMODEL * GK / 4 + 255) / 256, 256>>>(w_out, woh, wol, DMODEL * GK / 4);

    // 1) QKV projection: M=8192, N=2304 -> q/k/v fp32 regions of d_out
    {
        dim3 grid(3 * DMODEL / 128, MROWS / 128);
        mma_gemm_kernel<<<grid, 256, gemm_smem>>>(xh, xl, wih, wil, b_in, q_out, SBD);
    }

    // 2) attention (fp32 in from d_out, bf16 hi/lo mix out)
    {
        int smem = (128 * AST + 64 * AST + 64 * AST + 128 * AST) * (int)sizeof(float);
        cudaFuncSetAttribute(attn_kernel, cudaFuncAttributeMaxDynamicSharedMemorySize, smem);
        dim3 grid(S_LEN / 128, BATCH * NHEAD);
        attn_kernel<<<grid, 256, smem>>>(q_out, q_out + SBD, q_out + 2 * SBD, mixh, mixl);
    }

    // 3) output projection: M=8192, N=768
    {
        dim3 grid(DMODEL / 128, MROWS / 128);
        mma_gemm_kernel<<<grid, 256, gemm_smem>>>(mixh, mixl, woh, wol, b_out, o_out, 0);
    }
}

// round 13
// speedup vs baseline: 1.9147x; 1.9147x over previous
#include <cuda_runtime.h>
#include <cuda_bf16.h>
#include <math.h>
#include <stdint.h>

#define S_LEN 1024
#define BATCH 8
#define DMODEL 768
#define NHEAD 12
#define HDIM 64
#define PROMPT_NUM 8
#define TOKENS (S_LEN - PROMPT_NUM)           // 1016
#define MROWS (S_LEN * BATCH)                 // 8192
#define SBD ((size_t)S_LEN * BATCH * DMODEL)  // 6291456
#define GK DMODEL                             // K of both GEMMs = 768

// ---------------- bf16 split scratch (allocation-free rule) ----------------
__device__ __nv_bfloat16 g_xh[(size_t)MROWS * GK];
__device__ __nv_bfloat16 g_xl[(size_t)MROWS * GK];
__device__ __nv_bfloat16 g_wih[(size_t)3 * DMODEL * GK];
__device__ __nv_bfloat16 g_wil[(size_t)3 * DMODEL * GK];
__device__ __nv_bfloat16 g_woh[(size_t)DMODEL * GK];
__device__ __nv_bfloat16 g_wol[(size_t)DMODEL * GK];
__device__ __nv_bfloat16 g_mixh[(size_t)MROWS * DMODEL];
__device__ __nv_bfloat16 g_mixl[(size_t)MROWS * DMODEL];
__device__ __nv_bfloat16 g_qkvh[(size_t)3 * MROWS * DMODEL];
__device__ __nv_bfloat16 g_qkvl[(size_t)3 * MROWS * DMODEL];

// ---------------- PTX helpers (sm_80-class only: no tcgen05) ----------------
__device__ __forceinline__ uint32_t smem_u32(const void* p) {
    uint32_t a;
    asm("{ .reg .u64 t; cvta.to.shared.u64 t, %1; cvt.u32.u64 %0, t; }" : "=r"(a) : "l"(p));
    return a;
}

#define CP_ASYNC16(dst, src) \
    asm volatile("cp.async.cg.shared.global [%0], [%1], 16;" :: "r"(dst), "l"(src) : "memory")
#define CP_COMMIT() asm volatile("cp.async.commit_group;" ::: "memory")
#define CP_WAIT0() asm volatile("cp.async.wait_group 0;" ::: "memory")
#define CP_WAIT1() asm volatile("cp.async.wait_group 1;" ::: "memory")

__device__ __forceinline__ void ldmx4(uint32_t* r, uint32_t addr) {
    asm volatile("ldmatrix.sync.aligned.m8n8.x4.shared.b16 {%0,%1,%2,%3}, [%4];"
                 : "=r"(r[0]), "=r"(r[1]), "=r"(r[2]), "=r"(r[3]) : "r"(addr));
}
__device__ __forceinline__ void ldmx4t(uint32_t* r, uint32_t addr) {
    asm volatile("ldmatrix.sync.aligned.m8n8.x4.trans.shared.b16 {%0,%1,%2,%3}, [%4];"
                 : "=r"(r[0]), "=r"(r[1]), "=r"(r[2]), "=r"(r[3]) : "r"(addr));
}
__device__ __forceinline__ void ldmx2(uint32_t* r, uint32_t addr) {
    asm volatile("ldmatrix.sync.aligned.m8n8.x2.shared.b16 {%0,%1}, [%2];"
                 : "=r"(r[0]), "=r"(r[1]) : "r"(addr));
}
__device__ __forceinline__ void mma_bf16(float* c, const uint32_t* a, const uint32_t* b) {
    asm volatile(
        "mma.sync.aligned.m16n8k16.row.col.f32.bf16.bf16.f32 "
        "{%0,%1,%2,%3}, {%4,%5,%6,%7}, {%8,%9}, {%0,%1,%2,%3};"
        : "+f"(c[0]), "+f"(c[1]), "+f"(c[2]), "+f"(c[3])
        : "r"(a[0]), "r"(a[1]), "r"(a[2]), "r"(a[3]), "r"(b[0]), "r"(b[1]));
}

// pack two floats to bf16x2 (low = x) with residual pack
__device__ __forceinline__ void split2(float x, float y, uint32_t& hi, uint32_t& lo) {
    __nv_bfloat162 h = __floats2bfloat162_rn(x, y);
    hi = *(uint32_t*)&h;
    __nv_bfloat162 l = __floats2bfloat162_rn(x - __bfloat162float(h.x),
                                             y - __bfloat162float(h.y));
    lo = *(uint32_t*)&l;
}

// GEMM smem tile geometry: [128 rows][40 bf16] = 80 B/row, 10240 B/array
#define TROW 80
#define TBYTES 10240
#define STAGE (4 * TBYTES)   // Ah, Al, Bh, Bl per stage = 40960

// Attention smem row: 64 bf16 data padded to 72 elems = 144 B (rows shift 4 banks)
#define ATRB 144
#define AKV (64 * ATRB)      // 9216 per array

// ---------------- fp32 -> bf16 hi/lo split ----------------
__global__ __launch_bounds__(256) void convert_split_kernel(
    const float* __restrict__ in, __nv_bfloat16* __restrict__ hi,
    __nv_bfloat16* __restrict__ lo, int n4)
{
    int i = blockIdx.x * blockDim.x + threadIdx.x;
    if (i >= n4) return;
    float4 v = ((const float4*)in)[i];
    uint32_t h0, l0, h1, l1;
    split2(v.x, v.y, h0, l0);
    split2(v.z, v.w, h1, l1);
    ((uint32_t*)hi)[2 * i] = h0; ((uint32_t*)hi)[2 * i + 1] = h1;
    ((uint32_t*)lo)[2 * i] = l0; ((uint32_t*)lo)[2 * i + 1] = l1;
}

// ----------------------------------------------------------------------------
// mma.sync bf16 GEMM (proven R11/R12 core): C = (Ah+Al)(Bh+Bl)^T + bias.
// Optionally also emits C as bf16 hi/lo (biased) for the attention consumer.
// ----------------------------------------------------------------------------
__global__ __launch_bounds__(256, 2) void mma_gemm_kernel(
    const __nv_bfloat16* __restrict__ Ah_, const __nv_bfloat16* __restrict__ Al_,
    const __nv_bfloat16* __restrict__ Bh_, const __nv_bfloat16* __restrict__ Bl_,
    const float* __restrict__ bias, float* __restrict__ C,
    __nv_bfloat16* __restrict__ Ch, __nv_bfloat16* __restrict__ Cl,
    size_t region_stride)
{
    extern __shared__ char smem[];
    const uint32_t sb = smem_u32(smem);
    const int tid = threadIdx.x;
    const int wid = tid >> 5;
    const int lane = tid & 31;
    const int wm = wid & 1;
    const int wn = wid >> 1;
    const int row0 = blockIdx.y * 128;
    const int col0 = blockIdx.x * 128;

    const char* gA_h = (const char*)(Ah_ + (size_t)row0 * GK);
    const char* gA_l = (const char*)(Al_ + (size_t)row0 * GK);
    const char* gB_h = (const char*)(Bh_ + (size_t)col0 * GK);
    const char* gB_l = (const char*)(Bl_ + (size_t)col0 * GK);

    const int r0g = (tid + 0)   >> 2, g0 = (tid + 0)   & 3;
    const int r1g = (tid + 256) >> 2, g1 = (tid + 256) & 3;

#define LOAD_CHUNK(kc, stage) do {                                          \
        const uint32_t s0_ = sb + (stage) * STAGE;                          \
        {                                                                   \
            uint32_t d = (uint32_t)r0g * TROW + g0 * 16;                    \
            size_t src = (size_t)r0g * (GK * 2) + (size_t)(kc) * 64 + g0 * 16; \
            CP_ASYNC16(s0_ + 0 * TBYTES + d, gA_h + src);                   \
            CP_ASYNC16(s0_ + 1 * TBYTES + d, gA_l + src);                   \
            CP_ASYNC16(s0_ + 2 * TBYTES + d, gB_h + src);                   \
            CP_ASYNC16(s0_ + 3 * TBYTES + d, gB_l + src);                   \
        }                                                                   \
        {                                                                   \
            uint32_t d = (uint32_t)r1g * TROW + g1 * 16;                    \
            size_t src = (size_t)r1g * (GK * 2) + (size_t)(kc) * 64 + g1 * 16; \
            CP_ASYNC16(s0_ + 0 * TBYTES + d, gA_h + src);                   \
            CP_ASYNC16(s0_ + 1 * TBYTES + d, gA_l + src);                   \
            CP_ASYNC16(s0_ + 2 * TBYTES + d, gB_h + src);                   \
            CP_ASYNC16(s0_ + 3 * TBYTES + d, gB_l + src);                   \
        }                                                                   \
        CP_COMMIT();                                                        \
    } while (0)

    float acc[4][4][4];
#pragma unroll
    for (int im = 0; im < 4; im++)
#pragma unroll
        for (int jn = 0; jn < 4; jn++)
#pragma unroll
            for (int q = 0; q < 4; q++) acc[im][jn][q] = 0.0f;

    const uint32_t aoff = (uint32_t)(wm * 64 + (lane & 7) + ((lane >> 3) & 1) * 8) * TROW
                        + (uint32_t)(lane >> 4) * 16;
    const int l15 = lane & 15;
    const uint32_t boff = (uint32_t)(wn * 32 + (l15 & 7)) * TROW
                        + (uint32_t)((l15 >> 3) & 1) * 16;

    LOAD_CHUNK(0, 0);
    const int NKC = GK / 32;  // 24
    for (int kc = 0; kc < NKC; kc++) {
        if (kc + 1 < NKC) { LOAD_CHUNK(kc + 1, (kc + 1) & 1); CP_WAIT1(); }
        else              { CP_WAIT0(); }
        __syncthreads();

        const uint32_t s0 = sb + (kc & 1) * STAGE;
#pragma unroll
        for (int k16 = 0; k16 < 2; k16++) {
            const uint32_t kb = (uint32_t)k16 * 32;
            uint32_t bh[4][2], bl[4][2];
#pragma unroll
            for (int jn = 0; jn < 4; jn++) {
                ldmx2(bh[jn], s0 + 2 * TBYTES + boff + jn * 8 * TROW + kb);
                ldmx2(bl[jn], s0 + 3 * TBYTES + boff + jn * 8 * TROW + kb);
            }
#pragma unroll
            for (int im = 0; im < 4; im++) {
                uint32_t ah[4], al[4];
                ldmx4(ah, s0 + 0 * TBYTES + aoff + im * 16 * TROW + kb);
                ldmx4(al, s0 + 1 * TBYTES + aoff + im * 16 * TROW + kb);
#pragma unroll
                for (int jn = 0; jn < 4; jn++) {
                    mma_bf16(acc[im][jn], ah, bh[jn]);
                    mma_bf16(acc[im][jn], ah, bl[jn]);
                    mma_bf16(acc[im][jn], al, bh[jn]);
                }
            }
        }
        __syncthreads();
    }

    const int gid = lane >> 2, tq = lane & 3;
#pragma unroll
    for (int jn = 0; jn < 4; jn++) {
        const int colg = col0 + wn * 32 + jn * 8 + tq * 2;
        const int region = colg / DMODEL;
        const int cc = colg - region * DMODEL;
        float* Cb = C + (size_t)region * region_stride + cc;
        __nv_bfloat16* Chb = Ch ? Ch + (size_t)region * region_stride + cc : nullptr;
        __nv_bfloat16* Clb = Ch ? Cl + (size_t)region * region_stride + cc : nullptr;
        const float bx = bias[colg], by = bias[colg + 1];
#pragma unroll
        for (int im = 0; im < 4; im++) {
            const int rg = row0 + wm * 64 + im * 16 + gid;
            float2 v0, v1;
            v0.x = acc[im][jn][0] + bx; v0.y = acc[im][jn][1] + by;
            v1.x = acc[im][jn][2] + bx; v1.y = acc[im][jn][3] + by;
            *(float2*)(Cb + (size_t)rg * DMODEL) = v0;
            *(float2*)(Cb + (size_t)(rg + 8) * DMODEL) = v1;
            if (Chb) {
                uint32_t h0, l0, h1, l1;
                split2(v0.x, v0.y, h0, l0);
                split2(v1.x, v1.y, h1, l1);
                *(uint32_t*)(Chb + (size_t)rg * DMODEL) = h0;
                *(uint32_t*)(Clb + (size_t)rg * DMODEL) = l0;
                *(uint32_t*)(Chb + (size_t)(rg + 8) * DMODEL) = h1;
                *(uint32_t*)(Clb + (size_t)(rg + 8) * DMODEL) = l1;
            }
        }
    }
#undef LOAD_CHUNK
}

// ----------------------------------------------------------------------------
// mma.sync flash attention. Block = 128 q-rows of one (b,h); 8 warps x m16.
// S = 3-term bf16 (Qh Kh + Qh Kl + Ql Kh), softmax on fragments (quad shfl,
// zero cross-warp reductions), PV = 3-term (Ph Vh + Ph Vl + Pl Vh) with P
// converted in-register. K/V double-buffered cp.async; 1 sync per tile.
// ----------------------------------------------------------------------------
__global__ __launch_bounds__(256, 2) void attn_mma_kernel(
    const __nv_bfloat16* __restrict__ qkvh, const __nv_bfloat16* __restrict__ qkvl,
    __nv_bfloat16* __restrict__ mixh, __nv_bfloat16* __restrict__ mixl)
{
    extern __shared__ char smc[];
    const uint32_t sb = smem_u32(smc);
    const uint32_t sQh = sb;
    const uint32_t sQl = sQh + 128 * ATRB;           // +18432
    const uint32_t sKV = sQl + 128 * ATRB;           // +36864; buf: Kh,Kl,Vh,Vl (9216 each)

    const int tid = threadIdx.x;
    const int wid = tid >> 5;
    const int lane = tid & 31;
    const int bh = blockIdx.y;
    const int b = bh / NHEAD;
    const int h = bh - b * NHEAD;
    const int q0 = blockIdx.x * 128;

    const char* gqh = (const char*)qkvh;
    const char* gql = (const char*)qkvl;
    const char* gkh = (const char*)(qkvh + SBD);
    const char* gkl = (const char*)(qkvl + SBD);
    const char* gvh = (const char*)(qkvh + 2 * SBD);
    const char* gvl = (const char*)(qkvl + 2 * SBD);

    // cp.async granule mapping
    const int gr = tid >> 3;      // 0..31 (row within 256-granule batch: idx>>3 base)
    const int gg = (tid & 7) * 16;

    // prologue: Q (128 rows x 8 granules x hi/lo) + KV tile 0
#pragma unroll
    for (int i = 0; i < 4; i++) {
        const int r = gr + i * 32;
        const size_t off = (((size_t)(q0 + r) * BATCH + b) * DMODEL + h * HDIM) * 2 + gg;
        CP_ASYNC16(sQh + r * ATRB + gg, gqh + off);
        CP_ASYNC16(sQl + r * ATRB + gg, gql + off);
    }
#pragma unroll
    for (int i = 0; i < 2; i++) {
        const int r = gr + i * 32;
        const size_t off = (((size_t)r * BATCH + b) * DMODEL + h * HDIM) * 2 + gg;
        CP_ASYNC16(sKV + 0 * AKV + r * ATRB + gg, gkh + off);
        CP_ASYNC16(sKV + 1 * AKV + r * ATRB + gg, gkl + off);
        CP_ASYNC16(sKV + 2 * AKV + r * ATRB + gg, gvh + off);
        CP_ASYNC16(sKV + 3 * AKV + r * ATRB + gg, gvl + off);
    }
    CP_COMMIT();

    // fragment base offsets (byte)
    const uint32_t qoff = (uint32_t)(wid * 16 + (lane & 7) + ((lane >> 3) & 1) * 8) * ATRB
                        + (uint32_t)(lane >> 4) * 16;
    const uint32_t koff = (uint32_t)((lane & 7) + ((lane >> 4) & 1) * 8) * ATRB
                        + (uint32_t)((lane >> 3) & 1) * 16;
    const uint32_t voff = (uint32_t)((lane & 7) + ((lane >> 3) & 1) * 8) * ATRB
                        + (uint32_t)((lane >> 4) & 1) * 16;

    const int qrA = q0 + wid * 16 + (lane >> 2);
    const int qrB = qrA + 8;
    const bool qmA = (qrA == 0) || (qrA >= TOKENS);
    const bool qmB = (qrB == 0) || (qrB >= TOKENS);
    const int ncol = (lane & 3) * 2;   // n within 8-tile (pair base)

    float mA = -1e30f, mB = -1e30f, lsumA = 0.0f, lsumB = 0.0f;
    float o[8][4];
#pragma unroll
    for (int j = 0; j < 8; j++)
#pragma unroll
        for (int q = 0; q < 4; q++) o[j][q] = 0.0f;

    CP_WAIT0();
    __syncthreads();

    for (int kt = 0; kt < S_LEN; kt += 64) {
        const uint32_t sK = sKV + (((kt >> 6) & 1) ? 4 * AKV : 0);
        // issue next KV tile into other buffer
        if (kt + 64 < S_LEN) {
            const uint32_t sN = sKV + (((kt >> 6) & 1) ? 0 : 4 * AKV);
#pragma unroll
            for (int i = 0; i < 2; i++) {
                const int r = gr + i * 32;
                const size_t off =
                    (((size_t)(kt + 64 + r) * BATCH + b) * DMODEL + h * HDIM) * 2 + gg;
                CP_ASYNC16(sN + 0 * AKV + r * ATRB + gg, gkh + off);
                CP_ASYNC16(sN + 1 * AKV + r * ATRB + gg, gkl + off);
                CP_ASYNC16(sN + 2 * AKV + r * ATRB + gg, gvh + off);
                CP_ASYNC16(sN + 3 * AKV + r * ATRB + gg, gvl + off);
            }
            CP_COMMIT();
        }

        // ---- S = Q K^T (3-term) ----
        float s[8][4];
#pragma unroll
        for (int j = 0; j < 8; j++)
#pragma unroll
            for (int q = 0; q < 4; q++) s[j][q] = 0.0f;

#pragma unroll
        for (int kc = 0; kc < 4; kc++) {
            uint32_t q_h[4], q_l[4];
            ldmx4(q_h, sQh + qoff + kc * 32);
            ldmx4(q_l, sQl + qoff + kc * 32);
#pragma unroll
            for (int np = 0; np < 4; np++) {
                uint32_t k_h[4], k_l[4];
                ldmx4(k_h, sK + 0 * AKV + koff + np * 16 * ATRB + kc * 32);
                ldmx4(k_l, sK + 1 * AKV + koff + np * 16 * ATRB + kc * 32);
                mma_bf16(s[2 * np],     q_h, k_h + 0);
                mma_bf16(s[2 * np],     q_h, k_l + 0);
                mma_bf16(s[2 * np],     q_l, k_h + 0);
                mma_bf16(s[2 * np + 1], q_h, k_h + 2);
                mma_bf16(s[2 * np + 1], q_h, k_l + 2);
                mma_bf16(s[2 * np + 1], q_l, k_h + 2);
            }
        }

        // ---- scale + mask + row max (quad-distributed) ----
        float vmA = -1e30f, vmB = -1e30f;
#pragma unroll
        for (int j = 0; j < 8; j++) {
            const int n0 = kt + j * 8 + ncol;
            const bool k0m = n0 >= TOKENS, k1m = (n0 + 1) >= TOKENS;
            float t0 = s[j][0] * 0.125f; if (k0m && qmA) t0 = -10000.0f;
            float t1 = s[j][1] * 0.125f; if (k1m && qmA) t1 = -10000.0f;
            float t2 = s[j][2] * 0.125f; if (k0m && qmB) t2 = -10000.0f;
            float t3 = s[j][3] * 0.125f; if (k1m && qmB) t3 = -10000.0f;
            s[j][0] = t0; s[j][1] = t1; s[j][2] = t2; s[j][3] = t3;
            vmA = fmaxf(vmA, fmaxf(t0, t1));
            vmB = fmaxf(vmB, fmaxf(t2, t3));
        }
        vmA = fmaxf(vmA, __shfl_xor_sync(0xffffffffu, vmA, 1));
        vmA = fmaxf(vmA, __shfl_xor_sync(0xffffffffu, vmA, 2));
        vmB = fmaxf(vmB, __shfl_xor_sync(0xffffffffu, vmB, 1));
        vmB = fmaxf(vmB, __shfl_xor_sync(0xffffffffu, vmB, 2));

        const float nmA = fmaxf(mA, vmA), fA = __expf(mA - nmA);
        const float nmB = fmaxf(mB, vmB), fB = __expf(mB - nmB);
        mA = nmA; mB = nmB;
        lsumA *= fA; lsumB *= fB;

        float psA = 0.0f, psB = 0.0f;
#pragma unroll
        for (int j = 0; j < 8; j++) {
            float p0 = __expf(s[j][0] - mA), p1 = __expf(s[j][1] - mA);
            float p2 = __expf(s[j][2] - mB), p3 = __expf(s[j][3] - mB);
            s[j][0] = p0; s[j][1] = p1; s[j][2] = p2; s[j][3] = p3;
            psA += p0 + p1; psB += p2 + p3;
            o[j][0] *= fA; o[j][1] *= fA; o[j][2] *= fB; o[j][3] *= fB;
        }
        psA += __shfl_xor_sync(0xffffffffu, psA, 1);
        psA += __shfl_xor_sync(0xffffffffu, psA, 2);
        psB += __shfl_xor_sync(0xffffffffu, psB, 1);
        psB += __shfl_xor_sync(0xffffffffu, psB, 2);
        lsumA += psA; lsumB += psB;

        // ---- O += P V (3-term, P from registers) ----
#pragma unroll
        for (int kc = 0; kc < 4; kc++) {
            const int j0 = 2 * kc, j1 = 2 * kc + 1;
            uint32_t a_h[4], a_l[4];
            split2(s[j0][0], s[j0][1], a_h[0], a_l[0]);
            split2(s[j0][2], s[j0][3], a_h[1], a_l[1]);
            split2(s[j1][0], s[j1][1], a_h[2], a_l[2]);
            split2(s[j1][2], s[j1][3], a_h[3], a_l[3]);
#pragma unroll
            for (int np = 0; np < 4; np++) {
                uint32_t v_h[4], v_l[4];
                ldmx4t(v_h, sK + 2 * AKV + voff + kc * 16 * ATRB + np * 32);
                ldmx4t(v_l, sK + 3 * AKV + voff + kc * 16 * ATRB + np * 32);
                mma_bf16(o[2 * np],     a_h, v_h + 0);
                mma_bf16(o[2 * np],     a_h, v_l + 0);
                mma_bf16(o[2 * np],     a_l, v_h + 0);
                mma_bf16(o[2 * np + 1], a_h, v_h + 2);
                mma_bf16(o[2 * np + 1], a_h, v_l + 2);
                mma_bf16(o[2 * np + 1], a_l, v_h + 2);
            }
        }

        CP_WAIT0();
        __syncthreads();
    }

    // ---- epilogue: normalize, write mix bf16 hi/lo ----
    const float invA = 1.0f / lsumA, invB = 1.0f / lsumB;
    const size_t baseA = ((size_t)qrA * BATCH + b) * DMODEL + h * HDIM + ncol;
    const size_t baseB = ((size_t)qrB * BATCH + b) * DMODEL + h * HDIM + ncol;
#pragma unroll
    for (int j = 0; j < 8; j++) {
        uint32_t h0, l0, h1, l1;
        split2(o[j][0] * invA, o[j][1] * invA, h0, l0);
        split2(o[j][2] * invB, o[j][3] * invB, h1, l1);
        *(uint32_t*)(mixh + baseA + j * 8) = h0;
        *(uint32_t*)(mixl + baseA + j * 8) = l0;
        *(uint32_t*)(mixh + baseB + j * 8) = h1;
        *(uint32_t*)(mixl + baseB + j * 8) = l1;
    }
}

extern "C" void kernel_launch(void* const* d_in, const int* in_sizes, int n_in,
                              void* d_out, int out_size)
{
    const float* x      = (const float*)d_in[0];  // (S, B, D)
    const float* w_in   = (const float*)d_in[1];  // (3D, D)
    const float* b_in   = (const float*)d_in[2];  // (3D,)
    const float* w_out  = (const float*)d_in[3];  // (D, D)
    const float* b_out  = (const float*)d_in[4];  // (D,)
    float* out = (float*)d_out;

    float* q_out = out;            // q/k/v regions: [r=s*B+b][d]
    float* o_out = out + 3 * SBD;  // (S, B, D)

    __nv_bfloat16 *xh, *xl, *wih, *wil, *woh, *wol, *mixh, *mixl, *qkvh, *qkvl;
    cudaGetSymbolAddress((void**)&xh,   g_xh);
    cudaGetSymbolAddress((void**)&xl,   g_xl);
    cudaGetSymbolAddress((void**)&wih,  g_wih);
    cudaGetSymbolAddress((void**)&wil,  g_wil);
    cudaGetSymbolAddress((void**)&woh,  g_woh);
    cudaGetSymbolAddress((void**)&wol,  g_wol);
    cudaGetSymbolAddress((void**)&mixh, g_mixh);
    cudaGetSymbolAddress((void**)&mixl, g_mixl);
    cudaGetSymbolAddress((void**)&qkvh, g_qkvh);
    cudaGetSymbolAddress((void**)&qkvl, g_qkvl);

    const int gemm_smem = 2 * STAGE;          // 81920
    const int attn_smem = 2 * 128 * ATRB + 8 * AKV;  // 36864 + 73728 = 110592
    cudaFuncSetAttribute(mma_gemm_kernel, cudaFuncAttributeMaxDynamicSharedMemorySize, gemm_smem);
    cudaFuncSetAttribute(attn_mma_kernel, cudaFuncAttributeMaxDynamicSharedMemorySize, attn_smem);

    // 0) fp32 -> bf16 hi/lo splits
    convert_split_kernel<<<(MROWS * GK / 4 + 255) / 256, 256>>>(x, xh, xl, MROWS * GK / 4);
    convert_split_kernel<<<(3 * DMODEL * GK / 4 + 255) / 256, 256>>>(w_in, wih, wil, 3 * DMODEL * GK / 4);
    convert_split_kernel<<<(DMODEL * GK / 4 + 255) / 256, 256>>>(w_out, woh, wol, DMODEL * GK / 4);

    // 1) QKV projection -> fp32 q/k/v in d_out AND bf16 hi/lo copies
    {
        dim3 grid(3 * DMODEL / 128, MROWS / 128);
        mma_gemm_kernel<<<grid, 256, gemm_smem>>>(xh, xl, wih, wil, b_in, q_out,
                                                  qkvh, qkvl, SBD);
    }

    // 2) tensor-core flash attention (bf16 hi/lo in, bf16 hi/lo mix out)
    {
        dim3 grid(S_LEN / 128, BATCH * NHEAD);
        attn_mma_kernel<<<grid, 256, attn_smem>>>(qkvh, qkvl, mixh, mixl);
    }

    // 3) output projection
    {
        dim3 grid(DMODEL / 128, MROWS / 128);
        mma_gemm_kernel<<<grid, 256, gemm_smem>>>(mixh, mixl, woh, wol, b_out, o_out,
                                                  nullptr, nullptr, 0);
    }
}

// round 14
// speedup vs baseline: 2.2977x; 1.2000x over previous
#include <cuda_runtime.h>
#include <cuda_bf16.h>
#include <cuda_fp16.h>
#include <math.h>
#include <stdint.h>

#define S_LEN 1024
#define BATCH 8
#define DMODEL 768
#define NHEAD 12
#define HDIM 64
#define PROMPT_NUM 8
#define TOKENS (S_LEN - PROMPT_NUM)           // 1016
#define MROWS (S_LEN * BATCH)                 // 8192
#define SBD ((size_t)S_LEN * BATCH * DMODEL)  // 6291456
#define GK DMODEL                             // K of both GEMMs = 768

// ---------------- scratch (allocation-free rule) ----------------
__device__ __half g_xh[(size_t)MROWS * GK];        // x fp16 hi
__device__ __half g_xl[(size_t)MROWS * GK];        // x fp16 lo
__device__ __half g_wih[(size_t)3 * DMODEL * GK];  // w_in fp16 (single)
__device__ __half g_woh[(size_t)DMODEL * GK];      // w_out fp16 (single)
__device__ __half g_mixh[(size_t)MROWS * DMODEL];  // mix fp16 hi
__device__ __half g_mixl[(size_t)MROWS * DMODEL];  // mix fp16 lo
__device__ __nv_bfloat16 g_qkvh[(size_t)3 * MROWS * DMODEL];  // attention input (bf16 3-term)
__device__ __nv_bfloat16 g_qkvl[(size_t)3 * MROWS * DMODEL];

// ---------------- PTX helpers (sm_80-class only: no tcgen05) ----------------
__device__ __forceinline__ uint32_t smem_u32(const void* p) {
    uint32_t a;
    asm("{ .reg .u64 t; cvta.to.shared.u64 t, %1; cvt.u32.u64 %0, t; }" : "=r"(a) : "l"(p));
    return a;
}

#define CP_ASYNC16(dst, src) \
    asm volatile("cp.async.cg.shared.global [%0], [%1], 16;" :: "r"(dst), "l"(src) : "memory")
#define CP_COMMIT() asm volatile("cp.async.commit_group;" ::: "memory")
#define CP_WAIT0() asm volatile("cp.async.wait_group 0;" ::: "memory")
#define CP_WAIT1() asm volatile("cp.async.wait_group 1;" ::: "memory")

__device__ __forceinline__ void ldmx4(uint32_t* r, uint32_t addr) {
    asm volatile("ldmatrix.sync.aligned.m8n8.x4.shared.b16 {%0,%1,%2,%3}, [%4];"
                 : "=r"(r[0]), "=r"(r[1]), "=r"(r[2]), "=r"(r[3]) : "r"(addr));
}
__device__ __forceinline__ void ldmx4t(uint32_t* r, uint32_t addr) {
    asm volatile("ldmatrix.sync.aligned.m8n8.x4.trans.shared.b16 {%0,%1,%2,%3}, [%4];"
                 : "=r"(r[0]), "=r"(r[1]), "=r"(r[2]), "=r"(r[3]) : "r"(addr));
}
__device__ __forceinline__ void mma_bf16(float* c, const uint32_t* a, const uint32_t* b) {
    asm volatile(
        "mma.sync.aligned.m16n8k16.row.col.f32.bf16.bf16.f32 "
        "{%0,%1,%2,%3}, {%4,%5,%6,%7}, {%8,%9}, {%0,%1,%2,%3};"
        : "+f"(c[0]), "+f"(c[1]), "+f"(c[2]), "+f"(c[3])
        : "r"(a[0]), "r"(a[1]), "r"(a[2]), "r"(a[3]), "r"(b[0]), "r"(b[1]));
}
__device__ __forceinline__ void mma_f16(float* c, const uint32_t* a, const uint32_t* b) {
    asm volatile(
        "mma.sync.aligned.m16n8k16.row.col.f32.f16.f16.f32 "
        "{%0,%1,%2,%3}, {%4,%5,%6,%7}, {%8,%9}, {%0,%1,%2,%3};"
        : "+f"(c[0]), "+f"(c[1]), "+f"(c[2]), "+f"(c[3])
        : "r"(a[0]), "r"(a[1]), "r"(a[2]), "r"(a[3]), "r"(b[0]), "r"(b[1]));
}

// bf16 pair split (attention path)
__device__ __forceinline__ void split2(float x, float y, uint32_t& hi, uint32_t& lo) {
    __nv_bfloat162 h = __floats2bfloat162_rn(x, y);
    hi = *(uint32_t*)&h;
    __nv_bfloat162 l = __floats2bfloat162_rn(x - __bfloat162float(h.x),
                                             y - __bfloat162float(h.y));
    lo = *(uint32_t*)&l;
}
// fp16 pair split (GEMM activation path)
__device__ __forceinline__ void split2h(float x, float y, uint32_t& hi, uint32_t& lo) {
    __half hx = __float2half_rn(x), hy = __float2half_rn(y);
    __half2 hh = __halves2half2(hx, hy);
    hi = *(uint32_t*)&hh;
    __half lx = __float2half_rn(x - __half2float(hx));
    __half ly = __float2half_rn(y - __half2float(hy));
    __half2 ll = __halves2half2(lx, ly);
    lo = *(uint32_t*)&ll;
}

// GEMM smem tile geometry: [128 rows][40 elems] = 80 B/row, 10240 B/array
#define TROW 80
#define TBYTES 10240
#define STAGE (3 * TBYTES)   // Ah, Al, B per stage = 30720

// Attention smem row: 64 bf16 data padded to 72 elems = 144 B
#define ATRB 144
#define AKV (64 * ATRB)      // 9216 per array

// ---------------- converts ----------------
__global__ __launch_bounds__(256) void convert_split_h_kernel(
    const float* __restrict__ in, __half* __restrict__ hi,
    __half* __restrict__ lo, int n4)
{
    int i = blockIdx.x * blockDim.x + threadIdx.x;
    if (i >= n4) return;
    float4 v = ((const float4*)in)[i];
    uint32_t h0, l0, h1, l1;
    split2h(v.x, v.y, h0, l0);
    split2h(v.z, v.w, h1, l1);
    ((uint32_t*)hi)[2 * i] = h0; ((uint32_t*)hi)[2 * i + 1] = h1;
    ((uint32_t*)lo)[2 * i] = l0; ((uint32_t*)lo)[2 * i + 1] = l1;
}
__global__ __launch_bounds__(256) void convert_h_kernel(
    const float* __restrict__ in, __half* __restrict__ out, int n4)
{
    int i = blockIdx.x * blockDim.x + threadIdx.x;
    if (i >= n4) return;
    float4 v = ((const float4*)in)[i];
    __half2* O = (__half2*)out;
    O[2 * i]     = __floats2half2_rn(v.x, v.y);
    O[2 * i + 1] = __floats2half2_rn(v.z, v.w);
}

// ----------------------------------------------------------------------------
// 2-term fp16 mma.sync GEMM: C[r,n] = (Ah+Al)[r,:] . B16[n,:] + bias[n]
// A split to fp16 hi/lo (exact ~2^-21); B rounded once to fp16 (~1.4e-4 RMS).
// 128x128 CTA tile, 8 warps (2m x 4n), warp tile 64x32, BK=32, double-buffered
// cp.async. B fragments via merged x4 ldmatrix (2 per k16 covering 4 jn).
// Optional bf16 hi/lo side-output (for the attention consumer).
// ----------------------------------------------------------------------------
__global__ __launch_bounds__(256, 2) void mma_gemm_kernel(
    const __half* __restrict__ Ah_, const __half* __restrict__ Al_,
    const __half* __restrict__ B_,
    const float* __restrict__ bias, float* __restrict__ C,
    __nv_bfloat16* __restrict__ Ch, __nv_bfloat16* __restrict__ Cl,
    size_t region_stride)
{
    extern __shared__ char smem[];
    const uint32_t sb = smem_u32(smem);
    const int tid = threadIdx.x;
    const int wid = tid >> 5;
    const int lane = tid & 31;
    const int wm = wid & 1;
    const int wn = wid >> 1;
    const int row0 = blockIdx.y * 128;
    const int col0 = blockIdx.x * 128;

    const char* gA_h = (const char*)(Ah_ + (size_t)row0 * GK);
    const char* gA_l = (const char*)(Al_ + (size_t)row0 * GK);
    const char* gB   = (const char*)(B_  + (size_t)col0 * GK);

    const int r0g = (tid + 0)   >> 2, g0 = (tid + 0)   & 3;
    const int r1g = (tid + 256) >> 2, g1 = (tid + 256) & 3;

#define LOAD_CHUNK(kc, stage) do {                                          \
        const uint32_t s0_ = sb + (stage) * STAGE;                          \
        {                                                                   \
            uint32_t d = (uint32_t)r0g * TROW + g0 * 16;                    \
            size_t src = (size_t)r0g * (GK * 2) + (size_t)(kc) * 64 + g0 * 16; \
            CP_ASYNC16(s0_ + 0 * TBYTES + d, gA_h + src);                   \
            CP_ASYNC16(s0_ + 1 * TBYTES + d, gA_l + src);                   \
            CP_ASYNC16(s0_ + 2 * TBYTES + d, gB + src);                     \
        }                                                                   \
        {                                                                   \
            uint32_t d = (uint32_t)r1g * TROW + g1 * 16;                    \
            size_t src = (size_t)r1g * (GK * 2) + (size_t)(kc) * 64 + g1 * 16; \
            CP_ASYNC16(s0_ + 0 * TBYTES + d, gA_h + src);                   \
            CP_ASYNC16(s0_ + 1 * TBYTES + d, gA_l + src);                   \
            CP_ASYNC16(s0_ + 2 * TBYTES + d, gB + src);                     \
        }                                                                   \
        CP_COMMIT();                                                        \
    } while (0)

    float acc[4][4][4];
#pragma unroll
    for (int im = 0; im < 4; im++)
#pragma unroll
        for (int jn = 0; jn < 4; jn++)
#pragma unroll
            for (int q = 0; q < 4; q++) acc[im][jn][q] = 0.0f;

    // A x4: row = wm*64 + im*16 + (lane&7) + ((lane>>3)&1)*8, k-half = lane>>4
    const uint32_t aoff = (uint32_t)(wm * 64 + (lane & 7) + ((lane >> 3) & 1) * 8) * TROW
                        + (uint32_t)(lane >> 4) * 16;
    // B x4 (merged pair p covers jn=2p,2p+1):
    // row = wn*32 + p*16 + (lane&7) + ((lane>>4)&1)*8, k-half = (lane>>3)&1
    const uint32_t boff4 = (uint32_t)(wn * 32 + (lane & 7) + ((lane >> 4) & 1) * 8) * TROW
                         + (uint32_t)((lane >> 3) & 1) * 16;

    LOAD_CHUNK(0, 0);
    const int NKC = GK / 32;  // 24
    for (int kc = 0; kc < NKC; kc++) {
        if (kc + 1 < NKC) { LOAD_CHUNK(kc + 1, (kc + 1) & 1); CP_WAIT1(); }
        else              { CP_WAIT0(); }
        __syncthreads();

        const uint32_t s0 = sb + (kc & 1) * STAGE;
#pragma unroll
        for (int k16 = 0; k16 < 2; k16++) {
            const uint32_t kb = (uint32_t)k16 * 32;
            uint32_t bf[2][4];
            ldmx4(bf[0], s0 + 2 * TBYTES + boff4 + kb);                 // jn 0,1
            ldmx4(bf[1], s0 + 2 * TBYTES + boff4 + 16 * TROW + kb);     // jn 2,3
#pragma unroll
            for (int im = 0; im < 4; im++) {
                uint32_t ah[4], al[4];
                ldmx4(ah, s0 + 0 * TBYTES + aoff + im * 16 * TROW + kb);
                ldmx4(al, s0 + 1 * TBYTES + aoff + im * 16 * TROW + kb);
#pragma unroll
                for (int jn = 0; jn < 4; jn++) {
                    const uint32_t* b = &bf[jn >> 1][(jn & 1) * 2];
                    mma_f16(acc[im][jn], ah, b);
                    mma_f16(acc[im][jn], al, b);
                }
            }
        }
        __syncthreads();  // WAR guard
    }

    const int gid = lane >> 2, tq = lane & 3;
#pragma unroll
    for (int jn = 0; jn < 4; jn++) {
        const int colg = col0 + wn * 32 + jn * 8 + tq * 2;
        const int region = colg / DMODEL;
        const int cc = colg - region * DMODEL;
        float* Cb = C + (size_t)region * region_stride + cc;
        __nv_bfloat16* Chb = Ch ? Ch + (size_t)region * region_stride + cc : nullptr;
        __nv_bfloat16* Clb = Ch ? Cl + (size_t)region * region_stride + cc : nullptr;
        const float bx = bias[colg], by = bias[colg + 1];
#pragma unroll
        for (int im = 0; im < 4; im++) {
            const int rg = row0 + wm * 64 + im * 16 + gid;
            float2 v0, v1;
            v0.x = acc[im][jn][0] + bx; v0.y = acc[im][jn][1] + by;
            v1.x = acc[im][jn][2] + bx; v1.y = acc[im][jn][3] + by;
            *(float2*)(Cb + (size_t)rg * DMODEL) = v0;
            *(float2*)(Cb + (size_t)(rg + 8) * DMODEL) = v1;
            if (Chb) {
                uint32_t h0, l0, h1, l1;
                split2(v0.x, v0.y, h0, l0);
                split2(v1.x, v1.y, h1, l1);
                *(uint32_t*)(Chb + (size_t)rg * DMODEL) = h0;
                *(uint32_t*)(Clb + (size_t)rg * DMODEL) = l0;
                *(uint32_t*)(Chb + (size_t)(rg + 8) * DMODEL) = h1;
                *(uint32_t*)(Clb + (size_t)(rg + 8) * DMODEL) = l1;
            }
        }
    }
#undef LOAD_CHUNK
}

// ----------------------------------------------------------------------------
// mma.sync flash attention (proven R13 core, unchanged math). Epilogue now
// emits mix as fp16 hi/lo for the 2-term fp16 out-projection.
// ----------------------------------------------------------------------------
__global__ __launch_bounds__(256, 2) void attn_mma_kernel(
    const __nv_bfloat16* __restrict__ qkvh, const __nv_bfloat16* __restrict__ qkvl,
    __half* __restrict__ mixh, __half* __restrict__ mixl)
{
    extern __shared__ char smc[];
    const uint32_t sb = smem_u32(smc);
    const uint32_t sQh = sb;
    const uint32_t sQl = sQh + 128 * ATRB;
    const uint32_t sKV = sQl + 128 * ATRB;   // buffers: Kh,Kl,Vh,Vl (9216 each) x2

    const int tid = threadIdx.x;
    const int wid = tid >> 5;
    const int lane = tid & 31;
    const int bh = blockIdx.y;
    const int b = bh / NHEAD;
    const int h = bh - b * NHEAD;
    const int q0 = blockIdx.x * 128;

    const char* gqh = (const char*)qkvh;
    const char* gql = (const char*)qkvl;
    const char* gkh = (const char*)(qkvh + SBD);
    const char* gkl = (const char*)(qkvl + SBD);
    const char* gvh = (const char*)(qkvh + 2 * SBD);
    const char* gvl = (const char*)(qkvl + 2 * SBD);

    const int gr = tid >> 3;
    const int gg = (tid & 7) * 16;

#pragma unroll
    for (int i = 0; i < 4; i++) {
        const int r = gr + i * 32;
        const size_t off = (((size_t)(q0 + r) * BATCH + b) * DMODEL + h * HDIM) * 2 + gg;
        CP_ASYNC16(sQh + r * ATRB + gg, gqh + off);
        CP_ASYNC16(sQl + r * ATRB + gg, gql + off);
    }
#pragma unroll
    for (int i = 0; i < 2; i++) {
        const int r = gr + i * 32;
        const size_t off = (((size_t)r * BATCH + b) * DMODEL + h * HDIM) * 2 + gg;
        CP_ASYNC16(sKV + 0 * AKV + r * ATRB + gg, gkh + off);
        CP_ASYNC16(sKV + 1 * AKV + r * ATRB + gg, gkl + off);
        CP_ASYNC16(sKV + 2 * AKV + r * ATRB + gg, gvh + off);
        CP_ASYNC16(sKV + 3 * AKV + r * ATRB + gg, gvl + off);
    }
    CP_COMMIT();

    const uint32_t qoff = (uint32_t)(wid * 16 + (lane & 7) + ((lane >> 3) & 1) * 8) * ATRB
                        + (uint32_t)(lane >> 4) * 16;
    const uint32_t koff = (uint32_t)((lane & 7) + ((lane >> 4) & 1) * 8) * ATRB
                        + (uint32_t)((lane >> 3) & 1) * 16;
    const uint32_t voff = (uint32_t)((lane & 7) + ((lane >> 3) & 1) * 8) * ATRB
                        + (uint32_t)((lane >> 4) & 1) * 16;

    const int qrA = q0 + wid * 16 + (lane >> 2);
    const int qrB = qrA + 8;
    const bool qmA = (qrA == 0) || (qrA >= TOKENS);
    const bool qmB = (qrB == 0) || (qrB >= TOKENS);
    const int ncol = (lane & 3) * 2;

    float mA = -1e30f, mB = -1e30f, lsumA = 0.0f, lsumB = 0.0f;
    float o[8][4];
#pragma unroll
    for (int j = 0; j < 8; j++)
#pragma unroll
        for (int q = 0; q < 4; q++) o[j][q] = 0.0f;

    CP_WAIT0();
    __syncthreads();

    for (int kt = 0; kt < S_LEN; kt += 64) {
        const uint32_t sK = sKV + (((kt >> 6) & 1) ? 4 * AKV : 0);
        if (kt + 64 < S_LEN) {
            const uint32_t sN = sKV + (((kt >> 6) & 1) ? 0 : 4 * AKV);
#pragma unroll
            for (int i = 0; i < 2; i++) {
                const int r = gr + i * 32;
                const size_t off =
                    (((size_t)(kt + 64 + r) * BATCH + b) * DMODEL + h * HDIM) * 2 + gg;
                CP_ASYNC16(sN + 0 * AKV + r * ATRB + gg, gkh + off);
                CP_ASYNC16(sN + 1 * AKV + r * ATRB + gg, gkl + off);
                CP_ASYNC16(sN + 2 * AKV + r * ATRB + gg, gvh + off);
                CP_ASYNC16(sN + 3 * AKV + r * ATRB + gg, gvl + off);
            }
            CP_COMMIT();
        }

        // ---- S = Q K^T (3-term bf16) ----
        float s[8][4];
#pragma unroll
        for (int j = 0; j < 8; j++)
#pragma unroll
            for (int q = 0; q < 4; q++) s[j][q] = 0.0f;

#pragma unroll
        for (int kc = 0; kc < 4; kc++) {
            uint32_t q_h[4], q_l[4];
            ldmx4(q_h, sQh + qoff + kc * 32);
            ldmx4(q_l, sQl + qoff + kc * 32);
#pragma unroll
            for (int np = 0; np < 4; np++) {
                uint32_t k_h[4], k_l[4];
                ldmx4(k_h, sK + 0 * AKV + koff + np * 16 * ATRB + kc * 32);
                ldmx4(k_l, sK + 1 * AKV + koff + np * 16 * ATRB + kc * 32);
                mma_bf16(s[2 * np],     q_h, k_h + 0);
                mma_bf16(s[2 * np],     q_h, k_l + 0);
                mma_bf16(s[2 * np],     q_l, k_h + 0);
                mma_bf16(s[2 * np + 1], q_h, k_h + 2);
                mma_bf16(s[2 * np + 1], q_h, k_l + 2);
                mma_bf16(s[2 * np + 1], q_l, k_h + 2);
            }
        }

        float vmA = -1e30f, vmB = -1e30f;
#pragma unroll
        for (int j = 0; j < 8; j++) {
            const int n0 = kt + j * 8 + ncol;
            const bool k0m = n0 >= TOKENS, k1m = (n0 + 1) >= TOKENS;
            float t0 = s[j][0] * 0.125f; if (k0m && qmA) t0 = -10000.0f;
            float t1 = s[j][1] * 0.125f; if (k1m && qmA) t1 = -10000.0f;
            float t2 = s[j][2] * 0.125f; if (k0m && qmB) t2 = -10000.0f;
            float t3 = s[j][3] * 0.125f; if (k1m && qmB) t3 = -10000.0f;
            s[j][0] = t0; s[j][1] = t1; s[j][2] = t2; s[j][3] = t3;
            vmA = fmaxf(vmA, fmaxf(t0, t1));
            vmB = fmaxf(vmB, fmaxf(t2, t3));
        }
        vmA = fmaxf(vmA, __shfl_xor_sync(0xffffffffu, vmA, 1));
        vmA = fmaxf(vmA, __shfl_xor_sync(0xffffffffu, vmA, 2));
        vmB = fmaxf(vmB, __shfl_xor_sync(0xffffffffu, vmB, 1));
        vmB = fmaxf(vmB, __shfl_xor_sync(0xffffffffu, vmB, 2));

        const float nmA = fmaxf(mA, vmA), fA = __expf(mA - nmA);
        const float nmB = fmaxf(mB, vmB), fB = __expf(mB - nmB);
        mA = nmA; mB = nmB;
        lsumA *= fA; lsumB *= fB;

        float psA = 0.0f, psB = 0.0f;
#pragma unroll
        for (int j = 0; j < 8; j++) {
            float p0 = __expf(s[j][0] - mA), p1 = __expf(s[j][1] - mA);
            float p2 = __expf(s[j][2] - mB), p3 = __expf(s[j][3] - mB);
            s[j][0] = p0; s[j][1] = p1; s[j][2] = p2; s[j][3] = p3;
            psA += p0 + p1; psB += p2 + p3;
            o[j][0] *= fA; o[j][1] *= fA; o[j][2] *= fB; o[j][3] *= fB;
        }
        psA += __shfl_xor_sync(0xffffffffu, psA, 1);
        psA += __shfl_xor_sync(0xffffffffu, psA, 2);
        psB += __shfl_xor_sync(0xffffffffu, psB, 1);
        psB += __shfl_xor_sync(0xffffffffu, psB, 2);
        lsumA += psA; lsumB += psB;

        // ---- O += P V (3-term bf16, P from registers) ----
#pragma unroll
        for (int kc = 0; kc < 4; kc++) {
            const int j0 = 2 * kc, j1 = 2 * kc + 1;
            uint32_t a_h[4], a_l[4];
            split2(s[j0][0], s[j0][1], a_h[0], a_l[0]);
            split2(s[j0][2], s[j0][3], a_h[1], a_l[1]);
            split2(s[j1][0], s[j1][1], a_h[2], a_l[2]);
            split2(s[j1][2], s[j1][3], a_h[3], a_l[3]);
#pragma unroll
            for (int np = 0; np < 4; np++) {
                uint32_t v_h[4], v_l[4];
                ldmx4t(v_h, sK + 2 * AKV + voff + kc * 16 * ATRB + np * 32);
                ldmx4t(v_l, sK + 3 * AKV + voff + kc * 16 * ATRB + np * 32);
                mma_bf16(o[2 * np],     a_h, v_h + 0);
                mma_bf16(o[2 * np],     a_h, v_l + 0);
                mma_bf16(o[2 * np],     a_l, v_h + 0);
                mma_bf16(o[2 * np + 1], a_h, v_h + 2);
                mma_bf16(o[2 * np + 1], a_h, v_l + 2);
                mma_bf16(o[2 * np + 1], a_l, v_h + 2);
            }
        }

        CP_WAIT0();
        __syncthreads();
    }

    // ---- epilogue: normalize, write mix fp16 hi/lo ----
    const float invA = 1.0f / lsumA, invB = 1.0f / lsumB;
    const size_t baseA = ((size_t)qrA * BATCH + b) * DMODEL + h * HDIM + ncol;
    const size_t baseB = ((size_t)qrB * BATCH + b) * DMODEL + h * HDIM + ncol;
#pragma unroll
    for (int j = 0; j < 8; j++) {
        uint32_t h0, l0, h1, l1;
        split2h(o[j][0] * invA, o[j][1] * invA, h0, l0);
        split2h(o[j][2] * invB, o[j][3] * invB, h1, l1);
        *(uint32_t*)(mixh + baseA + j * 8) = h0;
        *(uint32_t*)(mixl + baseA + j * 8) = l0;
        *(uint32_t*)(mixh + baseB + j * 8) = h1;
        *(uint32_t*)(mixl + baseB + j * 8) = l1;
    }
}

extern "C" void kernel_launch(void* const* d_in, const int* in_sizes, int n_in,
                              void* d_out, int out_size)
{
    const float* x      = (const float*)d_in[0];  // (S, B, D)
    const float* w_in   = (const float*)d_in[1];  // (3D, D)
    const float* b_in   = (const float*)d_in[2];  // (3D,)
    const float* w_out  = (const float*)d_in[3];  // (D, D)
    const float* b_out  = (const float*)d_in[4];  // (D,)
    float* out = (float*)d_out;

    float* q_out = out;            // q/k/v regions: [r=s*B+b][d]
    float* o_out = out + 3 * SBD;  // (S, B, D)

    __half *xh, *xl, *wih, *woh, *mixh, *mixl;
    __nv_bfloat16 *qkvh, *qkvl;
    cudaGetSymbolAddress((void**)&xh,   g_xh);
    cudaGetSymbolAddress((void**)&xl,   g_xl);
    cudaGetSymbolAddress((void**)&wih,  g_wih);
    cudaGetSymbolAddress((void**)&woh,  g_woh);
    cudaGetSymbolAddress((void**)&mixh, g_mixh);
    cudaGetSymbolAddress((void**)&mixl, g_mixl);
    cudaGetSymbolAddress((void**)&qkvh, g_qkvh);
    cudaGetSymbolAddress((void**)&qkvl, g_qkvl);

    const int gemm_smem = 2 * STAGE;                 // 61440
    const int attn_smem = 2 * 128 * ATRB + 8 * AKV;  // 110592
    cudaFuncSetAttribute(mma_gemm_kernel, cudaFuncAttributeMaxDynamicSharedMemorySize, gemm_smem);
    cudaFuncSetAttribute(attn_mma_kernel, cudaFuncAttributeMaxDynamicSharedMemorySize, attn_smem);

    // 0) converts: x -> fp16 hi/lo; w_in, w_out -> fp16 single
    convert_split_h_kernel<<<(MROWS * GK / 4 + 255) / 256, 256>>>(x, xh, xl, MROWS * GK / 4);
    convert_h_kernel<<<(3 * DMODEL * GK / 4 + 255) / 256, 256>>>(w_in, wih, 3 * DMODEL * GK / 4);
    convert_h_kernel<<<(DMODEL * GK / 4 + 255) / 256, 256>>>(w_out, woh, DMODEL * GK / 4);

    // 1) QKV projection -> fp32 q/k/v in d_out + bf16 hi/lo for attention
    {
        dim3 grid(3 * DMODEL / 128, MROWS / 128);
        mma_gemm_kernel<<<grid, 256, gemm_smem>>>(xh, xl, wih, b_in, q_out,
                                                  qkvh, qkvl, SBD);
    }

    // 2) tensor-core flash attention (bf16 hi/lo in, fp16 hi/lo mix out)
    {
        dim3 grid(S_LEN / 128, BATCH * NHEAD);
        attn_mma_kernel<<<grid, 256, attn_smem>>>(qkvh, qkvl, mixh, mixl);
    }

    // 3) output projection
    {
        dim3 grid(DMODEL / 128, MROWS / 128);
        mma_gemm_kernel<<<grid, 256, gemm_smem>>>(mixh, mixl, woh, b_out, o_out,
                                                  nullptr, nullptr, 0);
    }
}

// round 15
// speedup vs baseline: 2.3119x; 1.0062x over previous
#include <cuda_runtime.h>
#include <cuda_bf16.h>
#include <cuda_fp16.h>
#include <math.h>
#include <stdint.h>

#define S_LEN 1024
#define BATCH 8
#define DMODEL 768
#define NHEAD 12
#define HDIM 64
#define PROMPT_NUM 8
#define TOKENS (S_LEN - PROMPT_NUM)           // 1016
#define MROWS (S_LEN * BATCH)                 // 8192
#define SBD ((size_t)S_LEN * BATCH * DMODEL)  // 6291456
#define GK DMODEL                             // K of both GEMMs = 768

// ---------------- scratch (allocation-free rule) ----------------
__device__ __half g_xh[(size_t)MROWS * GK];        // x fp16 hi
__device__ __half g_xl[(size_t)MROWS * GK];        // x fp16 lo
__device__ __half g_wih[(size_t)3 * DMODEL * GK];  // w_in fp16 (single)
__device__ __half g_woh[(size_t)DMODEL * GK];      // w_out fp16 (single)
__device__ __half g_mixh[(size_t)MROWS * DMODEL];  // mix fp16 hi
__device__ __half g_mixl[(size_t)MROWS * DMODEL];  // mix fp16 lo
__device__ __nv_bfloat16 g_qkvh[(size_t)3 * MROWS * DMODEL];  // attention input (bf16 3-term)
__device__ __nv_bfloat16 g_qkvl[(size_t)3 * MROWS * DMODEL];

// ---------------- PTX helpers (sm_80-class only: no tcgen05) ----------------
__device__ __forceinline__ uint32_t smem_u32(const void* p) {
    uint32_t a;
    asm("{ .reg .u64 t; cvta.to.shared.u64 t, %1; cvt.u32.u64 %0, t; }" : "=r"(a) : "l"(p));
    return a;
}

#define CP_ASYNC16(dst, src) \
    asm volatile("cp.async.cg.shared.global [%0], [%1], 16;" :: "r"(dst), "l"(src) : "memory")
#define CP_COMMIT() asm volatile("cp.async.commit_group;" ::: "memory")
#define CP_WAIT0() asm volatile("cp.async.wait_group 0;" ::: "memory")
#define CP_WAIT1() asm volatile("cp.async.wait_group 1;" ::: "memory")

__device__ __forceinline__ void ldmx4(uint32_t* r, uint32_t addr) {
    asm volatile("ldmatrix.sync.aligned.m8n8.x4.shared.b16 {%0,%1,%2,%3}, [%4];"
                 : "=r"(r[0]), "=r"(r[1]), "=r"(r[2]), "=r"(r[3]) : "r"(addr));
}
__device__ __forceinline__ void ldmx4t(uint32_t* r, uint32_t addr) {
    asm volatile("ldmatrix.sync.aligned.m8n8.x4.trans.shared.b16 {%0,%1,%2,%3}, [%4];"
                 : "=r"(r[0]), "=r"(r[1]), "=r"(r[2]), "=r"(r[3]) : "r"(addr));
}
__device__ __forceinline__ void mma_bf16(float* c, const uint32_t* a, const uint32_t* b) {
    asm volatile(
        "mma.sync.aligned.m16n8k16.row.col.f32.bf16.bf16.f32 "
        "{%0,%1,%2,%3}, {%4,%5,%6,%7}, {%8,%9}, {%0,%1,%2,%3};"
        : "+f"(c[0]), "+f"(c[1]), "+f"(c[2]), "+f"(c[3])
        : "r"(a[0]), "r"(a[1]), "r"(a[2]), "r"(a[3]), "r"(b[0]), "r"(b[1]));
}
__device__ __forceinline__ void mma_f16(float* c, const uint32_t* a, const uint32_t* b) {
    asm volatile(
        "mma.sync.aligned.m16n8k16.row.col.f32.f16.f16.f32 "
        "{%0,%1,%2,%3}, {%4,%5,%6,%7}, {%8,%9}, {%0,%1,%2,%3};"
        : "+f"(c[0]), "+f"(c[1]), "+f"(c[2]), "+f"(c[3])
        : "r"(a[0]), "r"(a[1]), "r"(a[2]), "r"(a[3]), "r"(b[0]), "r"(b[1]));
}

// bf16 pair split (attention path)
__device__ __forceinline__ void split2(float x, float y, uint32_t& hi, uint32_t& lo) {
    __nv_bfloat162 h = __floats2bfloat162_rn(x, y);
    hi = *(uint32_t*)&h;
    __nv_bfloat162 l = __floats2bfloat162_rn(x - __bfloat162float(h.x),
                                             y - __bfloat162float(h.y));
    lo = *(uint32_t*)&l;
}
// fp16 pair split (GEMM activation path)
__device__ __forceinline__ void split2h(float x, float y, uint32_t& hi, uint32_t& lo) {
    __half hx = __float2half_rn(x), hy = __float2half_rn(y);
    __half2 hh = __halves2half2(hx, hy);
    hi = *(uint32_t*)&hh;
    __half lx = __float2half_rn(x - __half2float(hx));
    __half ly = __float2half_rn(y - __half2float(hy));
    __half2 ll = __halves2half2(lx, ly);
    lo = *(uint32_t*)&ll;
}

// GEMM smem tile geometry: [128 rows][40 elems] = 80 B/row, 10240 B/array
#define TROW 80
#define TBYTES 10240
#define STAGE (3 * TBYTES)   // Ah, Al, B per stage = 30720; 3 stages = 92160

// Attention smem row: 64 bf16 data padded to 72 elems = 144 B
#define ATRB 144
#define AKV (64 * ATRB)      // 9216 per array

// ---------------- converts ----------------
__global__ __launch_bounds__(256) void convert_split_h_kernel(
    const float* __restrict__ in, __half* __restrict__ hi,
    __half* __restrict__ lo, int n4)
{
    int i = blockIdx.x * blockDim.x + threadIdx.x;
    if (i >= n4) return;
    float4 v = ((const float4*)in)[i];
    uint32_t h0, l0, h1, l1;
    split2h(v.x, v.y, h0, l0);
    split2h(v.z, v.w, h1, l1);
    ((uint32_t*)hi)[2 * i] = h0; ((uint32_t*)hi)[2 * i + 1] = h1;
    ((uint32_t*)lo)[2 * i] = l0; ((uint32_t*)lo)[2 * i + 1] = l1;
}
__global__ __launch_bounds__(256) void convert_h_kernel(
    const float* __restrict__ in, __half* __restrict__ out, int n4)
{
    int i = blockIdx.x * blockDim.x + threadIdx.x;
    if (i >= n4) return;
    float4 v = ((const float4*)in)[i];
    __half2* O = (__half2*)out;
    O[2 * i]     = __floats2half2_rn(v.x, v.y);
    O[2 * i + 1] = __floats2half2_rn(v.z, v.w);
}

// ----------------------------------------------------------------------------
// 2-term fp16 mma.sync GEMM: C[r,n] = (Ah+Al)[r,:] . B16[n,:] + bias[n]
// R15: 3-stage cp.async ring, ONE barrier per 32-k chunk.
//   iter kc: wait_group(1) [stage kc complete] -> __syncthreads() [all threads
//   done reading stage kc-1 == buffer (kc+2)%3] -> issue loads for kc+2 into
//   that buffer -> compute stage kc. Halves barrier count vs R14 and keeps
//   two chunks of loads in flight.
// ----------------------------------------------------------------------------
__global__ __launch_bounds__(256, 2) void mma_gemm_kernel(
    const __half* __restrict__ Ah_, const __half* __restrict__ Al_,
    const __half* __restrict__ B_,
    const float* __restrict__ bias, float* __restrict__ C,
    __nv_bfloat16* __restrict__ Ch, __nv_bfloat16* __restrict__ Cl,
    size_t region_stride)
{
    extern __shared__ char smem[];
    const uint32_t sb = smem_u32(smem);
    const int tid = threadIdx.x;
    const int wid = tid >> 5;
    const int lane = tid & 31;
    const int wm = wid & 1;
    const int wn = wid >> 1;
    const int row0 = blockIdx.y * 128;
    const int col0 = blockIdx.x * 128;

    const char* gA_h = (const char*)(Ah_ + (size_t)row0 * GK);
    const char* gA_l = (const char*)(Al_ + (size_t)row0 * GK);
    const char* gB   = (const char*)(B_  + (size_t)col0 * GK);

    const int r0g = (tid + 0)   >> 2, g0 = (tid + 0)   & 3;
    const int r1g = (tid + 256) >> 2, g1 = (tid + 256) & 3;

#define LOAD_CHUNK(kc, stage) do {                                          \
        const uint32_t s0_ = sb + (stage) * STAGE;                          \
        {                                                                   \
            uint32_t d = (uint32_t)r0g * TROW + g0 * 16;                    \
            size_t src = (size_t)r0g * (GK * 2) + (size_t)(kc) * 64 + g0 * 16; \
            CP_ASYNC16(s0_ + 0 * TBYTES + d, gA_h + src);                   \
            CP_ASYNC16(s0_ + 1 * TBYTES + d, gA_l + src);                   \
            CP_ASYNC16(s0_ + 2 * TBYTES + d, gB + src);                     \
        }                                                                   \
        {                                                                   \
            uint32_t d = (uint32_t)r1g * TROW + g1 * 16;                    \
            size_t src = (size_t)r1g * (GK * 2) + (size_t)(kc) * 64 + g1 * 16; \
            CP_ASYNC16(s0_ + 0 * TBYTES + d, gA_h + src);                   \
            CP_ASYNC16(s0_ + 1 * TBYTES + d, gA_l + src);                   \
            CP_ASYNC16(s0_ + 2 * TBYTES + d, gB + src);                     \
        }                                                                   \
        CP_COMMIT();                                                        \
    } while (0)

    float acc[4][4][4];
#pragma unroll
    for (int im = 0; im < 4; im++)
#pragma unroll
        for (int jn = 0; jn < 4; jn++)
#pragma unroll
            for (int q = 0; q < 4; q++) acc[im][jn][q] = 0.0f;

    // A x4: row = wm*64 + im*16 + (lane&7) + ((lane>>3)&1)*8, k-half = lane>>4
    const uint32_t aoff = (uint32_t)(wm * 64 + (lane & 7) + ((lane >> 3) & 1) * 8) * TROW
                        + (uint32_t)(lane >> 4) * 16;
    // B x4 (merged pair p covers jn=2p,2p+1)
    const uint32_t boff4 = (uint32_t)(wn * 32 + (lane & 7) + ((lane >> 4) & 1) * 8) * TROW
                         + (uint32_t)((lane >> 3) & 1) * 16;

    LOAD_CHUNK(0, 0);
    LOAD_CHUNK(1, 1);
    const int NKC = GK / 32;  // 24
    int stage = 0;            // kc % 3
    int wstage = 2;           // (kc+2) % 3
    for (int kc = 0; kc < NKC; kc++) {
        if (kc + 2 < NKC) CP_WAIT1();
        else              CP_WAIT0();
        __syncthreads();
        if (kc + 2 < NKC) LOAD_CHUNK(kc + 2, wstage);

        const uint32_t s0 = sb + stage * STAGE;
#pragma unroll
        for (int k16 = 0; k16 < 2; k16++) {
            const uint32_t kb = (uint32_t)k16 * 32;
            uint32_t bf[2][4];
            ldmx4(bf[0], s0 + 2 * TBYTES + boff4 + kb);                 // jn 0,1
            ldmx4(bf[1], s0 + 2 * TBYTES + boff4 + 16 * TROW + kb);     // jn 2,3
#pragma unroll
            for (int im = 0; im < 4; im++) {
                uint32_t ah[4], al[4];
                ldmx4(ah, s0 + 0 * TBYTES + aoff + im * 16 * TROW + kb);
                ldmx4(al, s0 + 1 * TBYTES + aoff + im * 16 * TROW + kb);
#pragma unroll
                for (int jn = 0; jn < 4; jn++) {
                    const uint32_t* b = &bf[jn >> 1][(jn & 1) * 2];
                    mma_f16(acc[im][jn], ah, b);
                    mma_f16(acc[im][jn], al, b);
                }
            }
        }
        stage = (stage == 2) ? 0 : stage + 1;
        wstage = (wstage == 2) ? 0 : wstage + 1;
    }

    const int gid = lane >> 2, tq = lane & 3;
#pragma unroll
    for (int jn = 0; jn < 4; jn++) {
        const int colg = col0 + wn * 32 + jn * 8 + tq * 2;
        const int region = colg / DMODEL;
        const int cc = colg - region * DMODEL;
        float* Cb = C + (size_t)region * region_stride + cc;
        __nv_bfloat16* Chb = Ch ? Ch + (size_t)region * region_stride + cc : nullptr;
        __nv_bfloat16* Clb = Ch ? Cl + (size_t)region * region_stride + cc : nullptr;
        const float bx = bias[colg], by = bias[colg + 1];
#pragma unroll
        for (int im = 0; im < 4; im++) {
            const int rg = row0 + wm * 64 + im * 16 + gid;
            float2 v0, v1;
            v0.x = acc[im][jn][0] + bx; v0.y = acc[im][jn][1] + by;
            v1.x = acc[im][jn][2] + bx; v1.y = acc[im][jn][3] + by;
            *(float2*)(Cb + (size_t)rg * DMODEL) = v0;
            *(float2*)(Cb + (size_t)(rg + 8) * DMODEL) = v1;
            if (Chb) {
                uint32_t h0, l0, h1, l1;
                split2(v0.x, v0.y, h0, l0);
                split2(v1.x, v1.y, h1, l1);
                *(uint32_t*)(Chb + (size_t)rg * DMODEL) = h0;
                *(uint32_t*)(Clb + (size_t)rg * DMODEL) = l0;
                *(uint32_t*)(Chb + (size_t)(rg + 8) * DMODEL) = h1;
                *(uint32_t*)(Clb + (size_t)(rg + 8) * DMODEL) = l1;
            }
        }
    }
#undef LOAD_CHUNK
}

// ----------------------------------------------------------------------------
// mma.sync flash attention (proven R13/R14 core, unchanged numerics).
// ----------------------------------------------------------------------------
__global__ __launch_bounds__(256, 2) void attn_mma_kernel(
    const __nv_bfloat16* __restrict__ qkvh, const __nv_bfloat16* __restrict__ qkvl,
    __half* __restrict__ mixh, __half* __restrict__ mixl)
{
    extern __shared__ char smc[];
    const uint32_t sb = smem_u32(smc);
    const uint32_t sQh = sb;
    const uint32_t sQl = sQh + 128 * ATRB;
    const uint32_t sKV = sQl + 128 * ATRB;   // buffers: Kh,Kl,Vh,Vl (9216 each) x2

    const int tid = threadIdx.x;
    const int wid = tid >> 5;
    const int lane = tid & 31;
    const int bh = blockIdx.y;
    const int b = bh / NHEAD;
    const int h = bh - b * NHEAD;
    const int q0 = blockIdx.x * 128;

    const char* gqh = (const char*)qkvh;
    const char* gql = (const char*)qkvl;
    const char* gkh = (const char*)(qkvh + SBD);
    const char* gkl = (const char*)(qkvl + SBD);
    const char* gvh = (const char*)(qkvh + 2 * SBD);
    const char* gvl = (const char*)(qkvl + 2 * SBD);

    const int gr = tid >> 3;
    const int gg = (tid & 7) * 16;

#pragma unroll
    for (int i = 0; i < 4; i++) {
        const int r = gr + i * 32;
        const size_t off = (((size_t)(q0 + r) * BATCH + b) * DMODEL + h * HDIM) * 2 + gg;
        CP_ASYNC16(sQh + r * ATRB + gg, gqh + off);
        CP_ASYNC16(sQl + r * ATRB + gg, gql + off);
    }
#pragma unroll
    for (int i = 0; i < 2; i++) {
        const int r = gr + i * 32;
        const size_t off = (((size_t)r * BATCH + b) * DMODEL + h * HDIM) * 2 + gg;
        CP_ASYNC16(sKV + 0 * AKV + r * ATRB + gg, gkh + off);
        CP_ASYNC16(sKV + 1 * AKV + r * ATRB + gg, gkl + off);
        CP_ASYNC16(sKV + 2 * AKV + r * ATRB + gg, gvh + off);
        CP_ASYNC16(sKV + 3 * AKV + r * ATRB + gg, gvl + off);
    }
    CP_COMMIT();

    const uint32_t qoff = (uint32_t)(wid * 16 + (lane & 7) + ((lane >> 3) & 1) * 8) * ATRB
                        + (uint32_t)(lane >> 4) * 16;
    const uint32_t koff = (uint32_t)((lane & 7) + ((lane >> 4) & 1) * 8) * ATRB
                        + (uint32_t)((lane >> 3) & 1) * 16;
    const uint32_t voff = (uint32_t)((lane & 7) + ((lane >> 3) & 1) * 8) * ATRB
                        + (uint32_t)((lane >> 4) & 1) * 16;

    const int qrA = q0 + wid * 16 + (lane >> 2);
    const int qrB = qrA + 8;
    const bool qmA = (qrA == 0) || (qrA >= TOKENS);
    const bool qmB = (qrB == 0) || (qrB >= TOKENS);
    const int ncol = (lane & 3) * 2;

    float mA = -1e30f, mB = -1e30f, lsumA = 0.0f, lsumB = 0.0f;
    float o[8][4];
#pragma unroll
    for (int j = 0; j < 8; j++)
#pragma unroll
        for (int q = 0; q < 4; q++) o[j][q] = 0.0f;

    CP_WAIT0();
    __syncthreads();

    for (int kt = 0; kt < S_LEN; kt += 64) {
        const uint32_t sK = sKV + (((kt >> 6) & 1) ? 4 * AKV : 0);
        if (kt + 64 < S_LEN) {
            const uint32_t sN = sKV + (((kt >> 6) & 1) ? 0 : 4 * AKV);
#pragma unroll
            for (int i = 0; i < 2; i++) {
                const int r = gr + i * 32;
                const size_t off =
                    (((size_t)(kt + 64 + r) * BATCH + b) * DMODEL + h * HDIM) * 2 + gg;
                CP_ASYNC16(sN + 0 * AKV + r * ATRB + gg, gkh + off);
                CP_ASYNC16(sN + 1 * AKV + r * ATRB + gg, gkl + off);
                CP_ASYNC16(sN + 2 * AKV + r * ATRB + gg, gvh + off);
                CP_ASYNC16(sN + 3 * AKV + r * ATRB + gg, gvl + off);
            }
            CP_COMMIT();
        }

        // ---- S = Q K^T (3-term bf16) ----
        float s[8][4];
#pragma unroll
        for (int j = 0; j < 8; j++)
#pragma unroll
            for (int q = 0; q < 4; q++) s[j][q] = 0.0f;

#pragma unroll
        for (int kc = 0; kc < 4; kc++) {
            uint32_t q_h[4], q_l[4];
            ldmx4(q_h, sQh + qoff + kc * 32);
            ldmx4(q_l, sQl + qoff + kc * 32);
#pragma unroll
            for (int np = 0; np < 4; np++) {
                uint32_t k_h[4], k_l[4];
                ldmx4(k_h, sK + 0 * AKV + koff + np * 16 * ATRB + kc * 32);
                ldmx4(k_l, sK + 1 * AKV + koff + np * 16 * ATRB + kc * 32);
                mma_bf16(s[2 * np],     q_h, k_h + 0);
                mma_bf16(s[2 * np],     q_h, k_l + 0);
                mma_bf16(s[2 * np],     q_l, k_h + 0);
                mma_bf16(s[2 * np + 1], q_h, k_h + 2);
                mma_bf16(s[2 * np + 1], q_h, k_l + 2);
                mma_bf16(s[2 * np + 1], q_l, k_h + 2);
            }
        }

        float vmA = -1e30f, vmB = -1e30f;
#pragma unroll
        for (int j = 0; j < 8; j++) {
            const int n0 = kt + j * 8 + ncol;
            const bool k0m = n0 >= TOKENS, k1m = (n0 + 1) >= TOKENS;
            float t0 = s[j][0] * 0.125f; if (k0m && qmA) t0 = -10000.0f;
            float t1 = s[j][1] * 0.125f; if (k1m && qmA) t1 = -10000.0f;
            float t2 = s[j][2] * 0.125f; if (k0m && qmB) t2 = -10000.0f;
            float t3 = s[j][3] * 0.125f; if (k1m && qmB) t3 = -10000.0f;
            s[j][0] = t0; s[j][1] = t1; s[j][2] = t2; s[j][3] = t3;
            vmA = fmaxf(vmA, fmaxf(t0, t1));
            vmB = fmaxf(vmB, fmaxf(t2, t3));
        }
        vmA = fmaxf(vmA, __shfl_xor_sync(0xffffffffu, vmA, 1));
        vmA = fmaxf(vmA, __shfl_xor_sync(0xffffffffu, vmA, 2));
        vmB = fmaxf(vmB, __shfl_xor_sync(0xffffffffu, vmB, 1));
        vmB = fmaxf(vmB, __shfl_xor_sync(0xffffffffu, vmB, 2));

        const float nmA = fmaxf(mA, vmA), fA = __expf(mA - nmA);
        const float nmB = fmaxf(mB, vmB), fB = __expf(mB - nmB);
        mA = nmA; mB = nmB;
        lsumA *= fA; lsumB *= fB;

        float psA = 0.0f, psB = 0.0f;
#pragma unroll
        for (int j = 0; j < 8; j++) {
            float p0 = __expf(s[j][0] - mA), p1 = __expf(s[j][1] - mA);
            float p2 = __expf(s[j][2] - mB), p3 = __expf(s[j][3] - mB);
            s[j][0] = p0; s[j][1] = p1; s[j][2] = p2; s[j][3] = p3;
            psA += p0 + p1; psB += p2 + p3;
            o[j][0] *= fA; o[j][1] *= fA; o[j][2] *= fB; o[j][3] *= fB;
        }
        psA += __shfl_xor_sync(0xffffffffu, psA, 1);
        psA += __shfl_xor_sync(0xffffffffu, psA, 2);
        psB += __shfl_xor_sync(0xffffffffu, psB, 1);
        psB += __shfl_xor_sync(0xffffffffu, psB, 2);
        lsumA += psA; lsumB += psB;

        // ---- O += P V (3-term bf16, P from registers) ----
#pragma unroll
        for (int kc = 0; kc < 4; kc++) {
            const int j0 = 2 * kc, j1 = 2 * kc + 1;
            uint32_t a_h[4], a_l[4];
            split2(s[j0][0], s[j0][1], a_h[0], a_l[0]);
            split2(s[j0][2], s[j0][3], a_h[1], a_l[1]);
            split2(s[j1][0], s[j1][1], a_h[2], a_l[2]);
            split2(s[j1][2], s[j1][3], a_h[3], a_l[3]);
#pragma unroll
            for (int np = 0; np < 4; np++) {
                uint32_t v_h[4], v_l[4];
                ldmx4t(v_h, sK + 2 * AKV + voff + kc * 16 * ATRB + np * 32);
                ldmx4t(v_l, sK + 3 * AKV + voff + kc * 16 * ATRB + np * 32);
                mma_bf16(o[2 * np],     a_h, v_h + 0);
                mma_bf16(o[2 * np],     a_h, v_l + 0);
                mma_bf16(o[2 * np],     a_l, v_h + 0);
                mma_bf16(o[2 * np + 1], a_h, v_h + 2);
                mma_bf16(o[2 * np + 1], a_h, v_l + 2);
                mma_bf16(o[2 * np + 1], a_l, v_h + 2);
            }
        }

        CP_WAIT0();
        __syncthreads();
    }

    // ---- epilogue: normalize, write mix fp16 hi/lo ----
    const float invA = 1.0f / lsumA, invB = 1.0f / lsumB;
    const size_t baseA = ((size_t)qrA * BATCH + b) * DMODEL + h * HDIM + ncol;
    const size_t baseB = ((size_t)qrB * BATCH + b) * DMODEL + h * HDIM + ncol;
#pragma unroll
    for (int j = 0; j < 8; j++) {
        uint32_t h0, l0, h1, l1;
        split2h(o[j][0] * invA, o[j][1] * invA, h0, l0);
        split2h(o[j][2] * invB, o[j][3] * invB, h1, l1);
        *(uint32_t*)(mixh + baseA + j * 8) = h0;
        *(uint32_t*)(mixl + baseA + j * 8) = l0;
        *(uint32_t*)(mixh + baseB + j * 8) = h1;
        *(uint32_t*)(mixl + baseB + j * 8) = l1;
    }
}

extern "C" void kernel_launch(void* const* d_in, const int* in_sizes, int n_in,
                              void* d_out, int out_size)
{
    const float* x      = (const float*)d_in[0];  // (S, B, D)
    const float* w_in   = (const float*)d_in[1];  // (3D, D)
    const float* b_in   = (const float*)d_in[2];  // (3D,)
    const float* w_out  = (const float*)d_in[3];  // (D, D)
    const float* b_out  = (const float*)d_in[4];  // (D,)
    float* out = (float*)d_out;

    float* q_out = out;            // q/k/v regions: [r=s*B+b][d]
    float* o_out = out + 3 * SBD;  // (S, B, D)

    __half *xh, *xl, *wih, *woh, *mixh, *mixl;
    __nv_bfloat16 *qkvh, *qkvl;
    cudaGetSymbolAddress((void**)&xh,   g_xh);
    cudaGetSymbolAddress((void**)&xl,   g_xl);
    cudaGetSymbolAddress((void**)&wih,  g_wih);
    cudaGetSymbolAddress((void**)&woh,  g_woh);
    cudaGetSymbolAddress((void**)&mixh, g_mixh);
    cudaGetSymbolAddress((void**)&mixl, g_mixl);
    cudaGetSymbolAddress((void**)&qkvh, g_qkvh);
    cudaGetSymbolAddress((void**)&qkvl, g_qkvl);

    const int gemm_smem = 3 * STAGE / 3 * 3;         // 92160 (3 stages)
    const int attn_smem = 2 * 128 * ATRB + 8 * AKV;  // 110592
    cudaFuncSetAttribute(mma_gemm_kernel, cudaFuncAttributeMaxDynamicSharedMemorySize, 3 * STAGE);
    cudaFuncSetAttribute(attn_mma_kernel, cudaFuncAttributeMaxDynamicSharedMemorySize, attn_smem);

    // 0) converts: x -> fp16 hi/lo; w_in, w_out -> fp16 single
    convert_split_h_kernel<<<(MROWS * GK / 4 + 255) / 256, 256>>>(x, xh, xl, MROWS * GK / 4);
    convert_h_kernel<<<(3 * DMODEL * GK / 4 + 255) / 256, 256>>>(w_in, wih, 3 * DMODEL * GK / 4);
    convert_h_kernel<<<(DMODEL * GK / 4 + 255) / 256, 256>>>(w_out, woh, DMODEL * GK / 4);

    // 1) QKV projection -> fp32 q/k/v in d_out + bf16 hi/lo for attention
    {
        dim3 grid(3 * DMODEL / 128, MROWS / 128);
        mma_gemm_kernel<<<grid, 256, 3 * STAGE>>>(xh, xl, wih, b_in, q_out,
                                                  qkvh, qkvl, SBD);
    }

    // 2) tensor-core flash attention (bf16 hi/lo in, fp16 hi/lo mix out)
    {
        dim3 grid(S_LEN / 128, BATCH * NHEAD);
        attn_mma_kernel<<<grid, 256, attn_smem>>>(qkvh, qkvl, mixh, mixl);
    }

    // 3) output projection
    {
        dim3 grid(DMODEL / 128, MROWS / 128);
        mma_gemm_kernel<<<grid, 256, 3 * STAGE>>>(mixh, mixl, woh, b_out, o_out,
                                                  nullptr, nullptr, 0);
    }
    (void)gemm_smem;
}

// round 16
// speedup vs baseline: 2.3283x; 1.0071x over previous
#include <cuda_runtime.h>
#include <cuda_bf16.h>
#include <cuda_fp16.h>
#include <math.h>
#include <stdint.h>

#define S_LEN 1024
#define BATCH 8
#define DMODEL 768
#define NHEAD 12
#define HDIM 64
#define PROMPT_NUM 8
#define TOKENS (S_LEN - PROMPT_NUM)           // 1016
#define MROWS (S_LEN * BATCH)                 // 8192
#define SBD ((size_t)S_LEN * BATCH * DMODEL)  // 6291456
#define GK DMODEL                             // K of both GEMMs = 768

// log2e and pre-scaled attention constants (log2-domain softmax)
#define LOG2E 1.4426950408889634f
#define SSCALE (0.125f * LOG2E)
#define MASKVAL (-10000.0f * LOG2E)

// ---------------- scratch (allocation-free rule) ----------------
__device__ __half g_xh[(size_t)MROWS * GK];        // x fp16 hi
__device__ __half g_xl[(size_t)MROWS * GK];        // x fp16 lo
__device__ __half g_wih[(size_t)3 * DMODEL * GK];  // w_in fp16 (single)
__device__ __half g_woh[(size_t)DMODEL * GK];      // w_out fp16 (single)
__device__ __half g_mixh[(size_t)MROWS * DMODEL];  // mix fp16 hi
__device__ __half g_mixl[(size_t)MROWS * DMODEL];  // mix fp16 lo
__device__ __nv_bfloat16 g_qkvh[(size_t)3 * MROWS * DMODEL];  // attention input (bf16 3-term)
__device__ __nv_bfloat16 g_qkvl[(size_t)3 * MROWS * DMODEL];

// ---------------- PTX helpers (sm_80-class only: no tcgen05) ----------------
__device__ __forceinline__ uint32_t smem_u32(const void* p) {
    uint32_t a;
    asm("{ .reg .u64 t; cvta.to.shared.u64 t, %1; cvt.u32.u64 %0, t; }" : "=r"(a) : "l"(p));
    return a;
}

#define CP_ASYNC16(dst, src) \
    asm volatile("cp.async.cg.shared.global [%0], [%1], 16;" :: "r"(dst), "l"(src) : "memory")
#define CP_COMMIT() asm volatile("cp.async.commit_group;" ::: "memory")
#define CP_WAIT0() asm volatile("cp.async.wait_group 0;" ::: "memory")
#define CP_WAIT1() asm volatile("cp.async.wait_group 1;" ::: "memory")

__device__ __forceinline__ void ldmx4(uint32_t* r, uint32_t addr) {
    asm volatile("ldmatrix.sync.aligned.m8n8.x4.shared.b16 {%0,%1,%2,%3}, [%4];"
                 : "=r"(r[0]), "=r"(r[1]), "=r"(r[2]), "=r"(r[3]) : "r"(addr));
}
__device__ __forceinline__ void ldmx4t(uint32_t* r, uint32_t addr) {
    asm volatile("ldmatrix.sync.aligned.m8n8.x4.trans.shared.b16 {%0,%1,%2,%3}, [%4];"
                 : "=r"(r[0]), "=r"(r[1]), "=r"(r[2]), "=r"(r[3]) : "r"(addr));
}
__device__ __forceinline__ void mma_bf16(float* c, const uint32_t* a, const uint32_t* b) {
    asm volatile(
        "mma.sync.aligned.m16n8k16.row.col.f32.bf16.bf16.f32 "
        "{%0,%1,%2,%3}, {%4,%5,%6,%7}, {%8,%9}, {%0,%1,%2,%3};"
        : "+f"(c[0]), "+f"(c[1]), "+f"(c[2]), "+f"(c[3])
        : "r"(a[0]), "r"(a[1]), "r"(a[2]), "r"(a[3]), "r"(b[0]), "r"(b[1]));
}
__device__ __forceinline__ void mma_f16(float* c, const uint32_t* a, const uint32_t* b) {
    asm volatile(
        "mma.sync.aligned.m16n8k16.row.col.f32.f16.f16.f32 "
        "{%0,%1,%2,%3}, {%4,%5,%6,%7}, {%8,%9}, {%0,%1,%2,%3};"
        : "+f"(c[0]), "+f"(c[1]), "+f"(c[2]), "+f"(c[3])
        : "r"(a[0]), "r"(a[1]), "r"(a[2]), "r"(a[3]), "r"(b[0]), "r"(b[1]));
}

// bf16 pair split (attention path)
__device__ __forceinline__ void split2(float x, float y, uint32_t& hi, uint32_t& lo) {
    __nv_bfloat162 h = __floats2bfloat162_rn(x, y);
    hi = *(uint32_t*)&h;
    __nv_bfloat162 l = __floats2bfloat162_rn(x - __bfloat162float(h.x),
                                             y - __bfloat162float(h.y));
    lo = *(uint32_t*)&l;
}
// fp16 pair split (GEMM activation path)
__device__ __forceinline__ void split2h(float x, float y, uint32_t& hi, uint32_t& lo) {
    __half hx = __float2half_rn(x), hy = __float2half_rn(y);
    __half2 hh = __halves2half2(hx, hy);
    hi = *(uint32_t*)&hh;
    __half lx = __float2half_rn(x - __half2float(hx));
    __half ly = __float2half_rn(y - __half2float(hy));
    __half2 ll = __halves2half2(lx, ly);
    lo = *(uint32_t*)&ll;
}

// GEMM smem tile geometry: [128 rows][40 elems] = 80 B/row, 10240 B/array
#define TROW 80
#define TBYTES 10240
#define STAGE (3 * TBYTES)   // Ah, Al, B per stage = 30720; 3 stages = 92160

// Attention smem row: 64 bf16 data padded to 72 elems = 144 B
#define ATRB 144
#define AKV (64 * ATRB)      // 9216 per array

// ---------------- converts ----------------
__global__ __launch_bounds__(256) void convert_split_h_kernel(
    const float* __restrict__ in, __half* __restrict__ hi,
    __half* __restrict__ lo, int n4)
{
    int i = blockIdx.x * blockDim.x + threadIdx.x;
    if (i >= n4) return;
    float4 v = ((const float4*)in)[i];
    uint32_t h0, l0, h1, l1;
    split2h(v.x, v.y, h0, l0);
    split2h(v.z, v.w, h1, l1);
    ((uint32_t*)hi)[2 * i] = h0; ((uint32_t*)hi)[2 * i + 1] = h1;
    ((uint32_t*)lo)[2 * i] = l0; ((uint32_t*)lo)[2 * i + 1] = l1;
}
__global__ __launch_bounds__(256) void convert_h_kernel(
    const float* __restrict__ in, __half* __restrict__ out, int n4)
{
    int i = blockIdx.x * blockDim.x + threadIdx.x;
    if (i >= n4) return;
    float4 v = ((const float4*)in)[i];
    __half2* O = (__half2*)out;
    O[2 * i]     = __floats2half2_rn(v.x, v.y);
    O[2 * i + 1] = __floats2half2_rn(v.z, v.w);
}

// ----------------------------------------------------------------------------
// 2-term fp16 mma.sync GEMM: C[r,n] = (Ah+Al)[r,:] . B16[n,:] + bias[n]
// 3-stage cp.async ring, one barrier per chunk. R16: fragment preloading —
// all 4 B frags for the chunk first, then per-im all 4 A frags, then 16
// back-to-back MMAs: long independent LDSM runs followed by independent HMMA
// runs (R15 interleaved dependent pairs -> latency-bound at 48% tensor).
// ----------------------------------------------------------------------------
__global__ __launch_bounds__(256, 2) void mma_gemm_kernel(
    const __half* __restrict__ Ah_, const __half* __restrict__ Al_,
    const __half* __restrict__ B_,
    const float* __restrict__ bias, float* __restrict__ C,
    __nv_bfloat16* __restrict__ Ch, __nv_bfloat16* __restrict__ Cl,
    size_t region_stride)
{
    extern __shared__ char smem[];
    const uint32_t sb = smem_u32(smem);
    const int tid = threadIdx.x;
    const int wid = tid >> 5;
    const int lane = tid & 31;
    const int wm = wid & 1;
    const int wn = wid >> 1;
    const int row0 = blockIdx.y * 128;
    const int col0 = blockIdx.x * 128;

    const char* gA_h = (const char*)(Ah_ + (size_t)row0 * GK);
    const char* gA_l = (const char*)(Al_ + (size_t)row0 * GK);
    const char* gB   = (const char*)(B_  + (size_t)col0 * GK);

    const int r0g = (tid + 0)   >> 2, g0 = (tid + 0)   & 3;
    const int r1g = (tid + 256) >> 2, g1 = (tid + 256) & 3;

#define LOAD_CHUNK(kc, stage) do {                                          \
        const uint32_t s0_ = sb + (stage) * STAGE;                          \
        {                                                                   \
            uint32_t d = (uint32_t)r0g * TROW + g0 * 16;                    \
            size_t src = (size_t)r0g * (GK * 2) + (size_t)(kc) * 64 + g0 * 16; \
            CP_ASYNC16(s0_ + 0 * TBYTES + d, gA_h + src);                   \
            CP_ASYNC16(s0_ + 1 * TBYTES + d, gA_l + src);                   \
            CP_ASYNC16(s0_ + 2 * TBYTES + d, gB + src);                     \
        }                                                                   \
        {                                                                   \
            uint32_t d = (uint32_t)r1g * TROW + g1 * 16;                    \
            size_t src = (size_t)r1g * (GK * 2) + (size_t)(kc) * 64 + g1 * 16; \
            CP_ASYNC16(s0_ + 0 * TBYTES + d, gA_h + src);                   \
            CP_ASYNC16(s0_ + 1 * TBYTES + d, gA_l + src);                   \
            CP_ASYNC16(s0_ + 2 * TBYTES + d, gB + src);                     \
        }                                                                   \
        CP_COMMIT();                                                        \
    } while (0)

    float acc[4][4][4];
#pragma unroll
    for (int im = 0; im < 4; im++)
#pragma unroll
        for (int jn = 0; jn < 4; jn++)
#pragma unroll
            for (int q = 0; q < 4; q++) acc[im][jn][q] = 0.0f;

    // A x4: row = wm*64 + im*16 + (lane&7) + ((lane>>3)&1)*8, k-half = lane>>4
    const uint32_t aoff = (uint32_t)(wm * 64 + (lane & 7) + ((lane >> 3) & 1) * 8) * TROW
                        + (uint32_t)(lane >> 4) * 16;
    // B x4 (merged pair p covers jn=2p,2p+1)
    const uint32_t boff4 = (uint32_t)(wn * 32 + (lane & 7) + ((lane >> 4) & 1) * 8) * TROW
                         + (uint32_t)((lane >> 3) & 1) * 16;

    LOAD_CHUNK(0, 0);
    LOAD_CHUNK(1, 1);
    const int NKC = GK / 32;  // 24
    int stage = 0;            // kc % 3
    int wstage = 2;           // (kc+2) % 3
    for (int kc = 0; kc < NKC; kc++) {
        if (kc + 2 < NKC) CP_WAIT1();
        else              CP_WAIT0();
        __syncthreads();
        if (kc + 2 < NKC) LOAD_CHUNK(kc + 2, wstage);

        const uint32_t s0 = sb + stage * STAGE;
        // preload ALL B fragments for the 32-k chunk (k16 halves 0 and 1)
        uint32_t bfr[4][4];   // [k16*2 + pair]
        ldmx4(bfr[0], s0 + 2 * TBYTES + boff4);                      // k0, jn 0,1
        ldmx4(bfr[1], s0 + 2 * TBYTES + boff4 + 16 * TROW);          // k0, jn 2,3
        ldmx4(bfr[2], s0 + 2 * TBYTES + boff4 + 32);                 // k1, jn 0,1
        ldmx4(bfr[3], s0 + 2 * TBYTES + boff4 + 16 * TROW + 32);     // k1, jn 2,3
#pragma unroll
        for (int im = 0; im < 4; im++) {
            uint32_t ah0[4], al0[4], ah1[4], al1[4];
            const uint32_t abase = aoff + (uint32_t)im * 16 * TROW;
            ldmx4(ah0, s0 + 0 * TBYTES + abase);
            ldmx4(al0, s0 + 1 * TBYTES + abase);
            ldmx4(ah1, s0 + 0 * TBYTES + abase + 32);
            ldmx4(al1, s0 + 1 * TBYTES + abase + 32);
#pragma unroll
            for (int jn = 0; jn < 4; jn++) {
                const uint32_t* b0 = &bfr[jn >> 1][(jn & 1) * 2];
                const uint32_t* b1 = &bfr[2 + (jn >> 1)][(jn & 1) * 2];
                mma_f16(acc[im][jn], ah0, b0);
                mma_f16(acc[im][jn], al0, b0);
                mma_f16(acc[im][jn], ah1, b1);
                mma_f16(acc[im][jn], al1, b1);
            }
        }
        stage = (stage == 2) ? 0 : stage + 1;
        wstage = (wstage == 2) ? 0 : wstage + 1;
    }

    const int gid = lane >> 2, tq = lane & 3;
#pragma unroll
    for (int jn = 0; jn < 4; jn++) {
        const int colg = col0 + wn * 32 + jn * 8 + tq * 2;
        const int region = colg / DMODEL;
        const int cc = colg - region * DMODEL;
        float* Cb = C + (size_t)region * region_stride + cc;
        __nv_bfloat16* Chb = Ch ? Ch + (size_t)region * region_stride + cc : nullptr;
        __nv_bfloat16* Clb = Ch ? Cl + (size_t)region * region_stride + cc : nullptr;
        const float bx = bias[colg], by = bias[colg + 1];
#pragma unroll
        for (int im = 0; im < 4; im++) {
            const int rg = row0 + wm * 64 + im * 16 + gid;
            float2 v0, v1;
            v0.x = acc[im][jn][0] + bx; v0.y = acc[im][jn][1] + by;
            v1.x = acc[im][jn][2] + bx; v1.y = acc[im][jn][3] + by;
            *(float2*)(Cb + (size_t)rg * DMODEL) = v0;
            *(float2*)(Cb + (size_t)(rg + 8) * DMODEL) = v1;
            if (Chb) {
                uint32_t h0, l0, h1, l1;
                split2(v0.x, v0.y, h0, l0);
                split2(v1.x, v1.y, h1, l1);
                *(uint32_t*)(Chb + (size_t)rg * DMODEL) = h0;
                *(uint32_t*)(Clb + (size_t)rg * DMODEL) = l0;
                *(uint32_t*)(Chb + (size_t)(rg + 8) * DMODEL) = h1;
                *(uint32_t*)(Clb + (size_t)(rg + 8) * DMODEL) = l1;
            }
        }
    }
#undef LOAD_CHUNK
}

// ----------------------------------------------------------------------------
// mma.sync flash attention (R13/R14 core). R16: log2-domain softmax (exp2f,
// scores pre-scaled by 0.125*log2e -> identical p values, one fewer mul per
// exponent) and masking hoisted out of all tiles except the last (keys >=
// TOKENS only exist in the final 64-key tile; branch is warp-uniform on kt).
// ----------------------------------------------------------------------------
__global__ __launch_bounds__(256, 2) void attn_mma_kernel(
    const __nv_bfloat16* __restrict__ qkvh, const __nv_bfloat16* __restrict__ qkvl,
    __half* __restrict__ mixh, __half* __restrict__ mixl)
{
    extern __shared__ char smc[];
    const uint32_t sb = smem_u32(smc);
    const uint32_t sQh = sb;
    const uint32_t sQl = sQh + 128 * ATRB;
    const uint32_t sKV = sQl + 128 * ATRB;   // buffers: Kh,Kl,Vh,Vl (9216 each) x2

    const int tid = threadIdx.x;
    const int wid = tid >> 5;
    const int lane = tid & 31;
    const int bh = blockIdx.y;
    const int b = bh / NHEAD;
    const int h = bh - b * NHEAD;
    const int q0 = blockIdx.x * 128;

    const char* gqh = (const char*)qkvh;
    const char* gql = (const char*)qkvl;
    const char* gkh = (const char*)(qkvh + SBD);
    const char* gkl = (const char*)(qkvl + SBD);
    const char* gvh = (const char*)(qkvh + 2 * SBD);
    const char* gvl = (const char*)(qkvl + 2 * SBD);

    const int gr = tid >> 3;
    const int gg = (tid & 7) * 16;

#pragma unroll
    for (int i = 0; i < 4; i++) {
        const int r = gr + i * 32;
        const size_t off = (((size_t)(q0 + r) * BATCH + b) * DMODEL + h * HDIM) * 2 + gg;
        CP_ASYNC16(sQh + r * ATRB + gg, gqh + off);
        CP_ASYNC16(sQl + r * ATRB + gg, gql + off);
    }
#pragma unroll
    for (int i = 0; i < 2; i++) {
        const int r = gr + i * 32;
        const size_t off = (((size_t)r * BATCH + b) * DMODEL + h * HDIM) * 2 + gg;
        CP_ASYNC16(sKV + 0 * AKV + r * ATRB + gg, gkh + off);
        CP_ASYNC16(sKV + 1 * AKV + r * ATRB + gg, gkl + off);
        CP_ASYNC16(sKV + 2 * AKV + r * ATRB + gg, gvh + off);
        CP_ASYNC16(sKV + 3 * AKV + r * ATRB + gg, gvl + off);
    }
    CP_COMMIT();

    const uint32_t qoff = (uint32_t)(wid * 16 + (lane & 7) + ((lane >> 3) & 1) * 8) * ATRB
                        + (uint32_t)(lane >> 4) * 16;
    const uint32_t koff = (uint32_t)((lane & 7) + ((lane >> 4) & 1) * 8) * ATRB
                        + (uint32_t)((lane >> 3) & 1) * 16;
    const uint32_t voff = (uint32_t)((lane & 7) + ((lane >> 3) & 1) * 8) * ATRB
                        + (uint32_t)((lane >> 4) & 1) * 16;

    const int qrA = q0 + wid * 16 + (lane >> 2);
    const int qrB = qrA + 8;
    const bool qmA = (qrA == 0) || (qrA >= TOKENS);
    const bool qmB = (qrB == 0) || (qrB >= TOKENS);
    const int ncol = (lane & 3) * 2;

    float mA = -1e30f, mB = -1e30f, lsumA = 0.0f, lsumB = 0.0f;
    float o[8][4];
#pragma unroll
    for (int j = 0; j < 8; j++)
#pragma unroll
        for (int q = 0; q < 4; q++) o[j][q] = 0.0f;

    CP_WAIT0();
    __syncthreads();

    for (int kt = 0; kt < S_LEN; kt += 64) {
        const uint32_t sK = sKV + (((kt >> 6) & 1) ? 4 * AKV : 0);
        if (kt + 64 < S_LEN) {
            const uint32_t sN = sKV + (((kt >> 6) & 1) ? 0 : 4 * AKV);
#pragma unroll
            for (int i = 0; i < 2; i++) {
                const int r = gr + i * 32;
                const size_t off =
                    (((size_t)(kt + 64 + r) * BATCH + b) * DMODEL + h * HDIM) * 2 + gg;
                CP_ASYNC16(sN + 0 * AKV + r * ATRB + gg, gkh + off);
                CP_ASYNC16(sN + 1 * AKV + r * ATRB + gg, gkl + off);
                CP_ASYNC16(sN + 2 * AKV + r * ATRB + gg, gvh + off);
                CP_ASYNC16(sN + 3 * AKV + r * ATRB + gg, gvl + off);
            }
            CP_COMMIT();
        }

        // ---- S = Q K^T (3-term bf16) ----
        float s[8][4];
#pragma unroll
        for (int j = 0; j < 8; j++)
#pragma unroll
            for (int q = 0; q < 4; q++) s[j][q] = 0.0f;

#pragma unroll
        for (int kc = 0; kc < 4; kc++) {
            uint32_t q_h[4], q_l[4];
            ldmx4(q_h, sQh + qoff + kc * 32);
            ldmx4(q_l, sQl + qoff + kc * 32);
#pragma unroll
            for (int np = 0; np < 4; np++) {
                uint32_t k_h[4], k_l[4];
                ldmx4(k_h, sK + 0 * AKV + koff + np * 16 * ATRB + kc * 32);
                ldmx4(k_l, sK + 1 * AKV + koff + np * 16 * ATRB + kc * 32);
                mma_bf16(s[2 * np],     q_h, k_h + 0);
                mma_bf16(s[2 * np],     q_h, k_l + 0);
                mma_bf16(s[2 * np],     q_l, k_h + 0);
                mma_bf16(s[2 * np + 1], q_h, k_h + 2);
                mma_bf16(s[2 * np + 1], q_h, k_l + 2);
                mma_bf16(s[2 * np + 1], q_l, k_h + 2);
            }
        }

        // ---- scale (+mask on last tile only) + row max ----
        float vmA = -1e30f, vmB = -1e30f;
        if (kt + 64 >= S_LEN) {
            // last tile: contains keys >= TOKENS
#pragma unroll
            for (int j = 0; j < 8; j++) {
                const int n0 = kt + j * 8 + ncol;
                const bool k0m = n0 >= TOKENS, k1m = (n0 + 1) >= TOKENS;
                float t0 = s[j][0] * SSCALE; if (k0m && qmA) t0 = MASKVAL;
                float t1 = s[j][1] * SSCALE; if (k1m && qmA) t1 = MASKVAL;
                float t2 = s[j][2] * SSCALE; if (k0m && qmB) t2 = MASKVAL;
                float t3 = s[j][3] * SSCALE; if (k1m && qmB) t3 = MASKVAL;
                s[j][0] = t0; s[j][1] = t1; s[j][2] = t2; s[j][3] = t3;
                vmA = fmaxf(vmA, fmaxf(t0, t1));
                vmB = fmaxf(vmB, fmaxf(t2, t3));
            }
        } else {
#pragma unroll
            for (int j = 0; j < 8; j++) {
                float t0 = s[j][0] * SSCALE;
                float t1 = s[j][1] * SSCALE;
                float t2 = s[j][2] * SSCALE;
                float t3 = s[j][3] * SSCALE;
                s[j][0] = t0; s[j][1] = t1; s[j][2] = t2; s[j][3] = t3;
                vmA = fmaxf(vmA, fmaxf(t0, t1));
                vmB = fmaxf(vmB, fmaxf(t2, t3));
            }
        }
        vmA = fmaxf(vmA, __shfl_xor_sync(0xffffffffu, vmA, 1));
        vmA = fmaxf(vmA, __shfl_xor_sync(0xffffffffu, vmA, 2));
        vmB = fmaxf(vmB, __shfl_xor_sync(0xffffffffu, vmB, 1));
        vmB = fmaxf(vmB, __shfl_xor_sync(0xffffffffu, vmB, 2));

        const float nmA = fmaxf(mA, vmA), fA = exp2f(mA - nmA);
        const float nmB = fmaxf(mB, vmB), fB = exp2f(mB - nmB);
        mA = nmA; mB = nmB;
        lsumA *= fA; lsumB *= fB;

        float psA = 0.0f, psB = 0.0f;
#pragma unroll
        for (int j = 0; j < 8; j++) {
            float p0 = exp2f(s[j][0] - mA), p1 = exp2f(s[j][1] - mA);
            float p2 = exp2f(s[j][2] - mB), p3 = exp2f(s[j][3] - mB);
            s[j][0] = p0; s[j][1] = p1; s[j][2] = p2; s[j][3] = p3;
            psA += p0 + p1; psB += p2 + p3;
            o[j][0] *= fA; o[j][1] *= fA; o[j][2] *= fB; o[j][3] *= fB;
        }
        psA += __shfl_xor_sync(0xffffffffu, psA, 1);
        psA += __shfl_xor_sync(0xffffffffu, psA, 2);
        psB += __shfl_xor_sync(0xffffffffu, psB, 1);
        psB += __shfl_xor_sync(0xffffffffu, psB, 2);
        lsumA += psA; lsumB += psB;

        // ---- O += P V (3-term bf16, P from registers) ----
#pragma unroll
        for (int kc = 0; kc < 4; kc++) {
            const int j0 = 2 * kc, j1 = 2 * kc + 1;
            uint32_t a_h[4], a_l[4];
            split2(s[j0][0], s[j0][1], a_h[0], a_l[0]);
            split2(s[j0][2], s[j0][3], a_h[1], a_l[1]);
            split2(s[j1][0], s[j1][1], a_h[2], a_l[2]);
            split2(s[j1][2], s[j1][3], a_h[3], a_l[3]);
#pragma unroll
            for (int np = 0; np < 4; np++) {
                uint32_t v_h[4], v_l[4];
                ldmx4t(v_h, sK + 2 * AKV + voff + kc * 16 * ATRB + np * 32);
                ldmx4t(v_l, sK + 3 * AKV + voff + kc * 16 * ATRB + np * 32);
                mma_bf16(o[2 * np],     a_h, v_h + 0);
                mma_bf16(o[2 * np],     a_h, v_l + 0);
                mma_bf16(o[2 * np],     a_l, v_h + 0);
                mma_bf16(o[2 * np + 1], a_h, v_h + 2);
                mma_bf16(o[2 * np + 1], a_h, v_l + 2);
                mma_bf16(o[2 * np + 1], a_l, v_h + 2);
            }
        }

        CP_WAIT0();
        __syncthreads();
    }

    // ---- epilogue: normalize, write mix fp16 hi/lo ----
    const float invA = 1.0f / lsumA, invB = 1.0f / lsumB;
    const size_t baseA = ((size_t)qrA * BATCH + b) * DMODEL + h * HDIM + ncol;
    const size_t baseB = ((size_t)qrB * BATCH + b) * DMODEL + h * HDIM + ncol;
#pragma unroll
    for (int j = 0; j < 8; j++) {
        uint32_t h0, l0, h1, l1;
        split2h(o[j][0] * invA, o[j][1] * invA, h0, l0);
        split2h(o[j][2] * invB, o[j][3] * invB, h1, l1);
        *(uint32_t*)(mixh + baseA + j * 8) = h0;
        *(uint32_t*)(mixl + baseA + j * 8) = l0;
        *(uint32_t*)(mixh + baseB + j * 8) = h1;
        *(uint32_t*)(mixl + baseB + j * 8) = l1;
    }
}

extern "C" void kernel_launch(void* const* d_in, const int* in_sizes, int n_in,
                              void* d_out, int out_size)
{
    const float* x      = (const float*)d_in[0];  // (S, B, D)
    const float* w_in   = (const float*)d_in[1];  // (3D, D)
    const float* b_in   = (const float*)d_in[2];  // (3D,)
    const float* w_out  = (const float*)d_in[3];  // (D, D)
    const float* b_out  = (const float*)d_in[4];  // (D,)
    float* out = (float*)d_out;

    float* q_out = out;            // q/k/v regions: [r=s*B+b][d]
    float* o_out = out + 3 * SBD;  // (S, B, D)

    __half *xh, *xl, *wih, *woh, *mixh, *mixl;
    __nv_bfloat16 *qkvh, *qkvl;
    cudaGetSymbolAddress((void**)&xh,   g_xh);
    cudaGetSymbolAddress((void**)&xl,   g_xl);
    cudaGetSymbolAddress((void**)&wih,  g_wih);
    cudaGetSymbolAddress((void**)&woh,  g_woh);
    cudaGetSymbolAddress((void**)&mixh, g_mixh);
    cudaGetSymbolAddress((void**)&mixl, g_mixl);
    cudaGetSymbolAddress((void**)&qkvh, g_qkvh);
    cudaGetSymbolAddress((void**)&qkvl, g_qkvl);

    const int gemm_smem = 3 * STAGE;                 // 92160
    const int attn_smem = 2 * 128 * ATRB + 8 * AKV;  // 110592
    cudaFuncSetAttribute(mma_gemm_kernel, cudaFuncAttributeMaxDynamicSharedMemorySize, gemm_smem);
    cudaFuncSetAttribute(attn_mma_kernel, cudaFuncAttributeMaxDynamicSharedMemorySize, attn_smem);

    // 0) converts: x -> fp16 hi/lo; w_in, w_out -> fp16 single
    convert_split_h_kernel<<<(MROWS * GK / 4 + 255) / 256, 256>>>(x, xh, xl, MROWS * GK / 4);
    convert_h_kernel<<<(3 * DMODEL * GK / 4 + 255) / 256, 256>>>(w_in, wih, 3 * DMODEL * GK / 4);
    convert_h_kernel<<<(DMODEL * GK / 4 + 255) / 256, 256>>>(w_out, woh, DMODEL * GK / 4);

    // 1) QKV projection -> fp32 q/k/v in d_out + bf16 hi/lo for attention
    {
        dim3 grid(3 * DMODEL / 128, MROWS / 128);
        mma_gemm_kernel<<<grid, 256, gemm_smem>>>(xh, xl, wih, b_in, q_out,
                                                  qkvh, qkvl, SBD);
    }

    // 2) tensor-core flash attention (bf16 hi/lo in, fp16 hi/lo mix out)
    {
        dim3 grid(S_LEN / 128, BATCH * NHEAD);
        attn_mma_kernel<<<grid, 256, attn_smem>>>(qkvh, qkvl, mixh, mixl);
    }

    // 3) output projection
    {
        dim3 grid(DMODEL / 128, MROWS / 128);
        mma_gemm_kernel<<<grid, 256, gemm_smem>>>(mixh, mixl, woh, b_out, o_out,
                                                  nullptr, nullptr, 0);
    }
}

// round 17
// speedup vs baseline: 2.4109x; 1.0355x over previous
#include <cuda_runtime.h>
#include <cuda_bf16.h>
#include <cuda_fp16.h>
#include <math.h>
#include <stdint.h>

#define S_LEN 1024
#define BATCH 8
#define DMODEL 768
#define NHEAD 12
#define HDIM 64
#define PROMPT_NUM 8
#define TOKENS (S_LEN - PROMPT_NUM)           // 1016
#define MROWS (S_LEN * BATCH)                 // 8192
#define SBD ((size_t)S_LEN * BATCH * DMODEL)  // 6291456
#define GK DMODEL                             // K of both GEMMs = 768

// log2-domain softmax constants
#define LOG2E 1.4426950408889634f
#define SSCALE (0.125f * LOG2E)
#define MASKVAL (-10000.0f * LOG2E)

// ---------------- scratch (allocation-free rule) ----------------
__device__ __half g_xh[(size_t)MROWS * GK];        // x fp16 hi
__device__ __half g_xl[(size_t)MROWS * GK];        // x fp16 lo
__device__ __half g_wih[(size_t)3 * DMODEL * GK];  // w_in fp16 (single)
__device__ __half g_woh[(size_t)DMODEL * GK];      // w_out fp16 (single)
__device__ __half g_mixh[(size_t)MROWS * DMODEL];  // mix fp16 hi
__device__ __half g_mixl[(size_t)MROWS * DMODEL];  // mix fp16 lo
__device__ __nv_bfloat16 g_qkvh[(size_t)3 * MROWS * DMODEL];  // attention input
__device__ __nv_bfloat16 g_qkvl[(size_t)3 * MROWS * DMODEL];

// ---------------- PTX helpers ----------------
__device__ __forceinline__ uint32_t smem_u32(const void* p) {
    uint32_t a;
    asm("{ .reg .u64 t; cvta.to.shared.u64 t, %1; cvt.u32.u64 %0, t; }" : "=r"(a) : "l"(p));
    return a;
}

#define CP_ASYNC16(dst, src) \
    asm volatile("cp.async.cg.shared.global [%0], [%1], 16;" :: "r"(dst), "l"(src) : "memory")
#define CP_COMMIT() asm volatile("cp.async.commit_group;" ::: "memory")
#define CP_WAIT0() asm volatile("cp.async.wait_group 0;" ::: "memory")
#define CP_WAIT1() asm volatile("cp.async.wait_group 1;" ::: "memory")

__device__ __forceinline__ void ldmx4(uint32_t* r, uint32_t addr) {
    asm volatile("ldmatrix.sync.aligned.m8n8.x4.shared.b16 {%0,%1,%2,%3}, [%4];"
                 : "=r"(r[0]), "=r"(r[1]), "=r"(r[2]), "=r"(r[3]) : "r"(addr));
}
__device__ __forceinline__ void ldmx4t(uint32_t* r, uint32_t addr) {
    asm volatile("ldmatrix.sync.aligned.m8n8.x4.trans.shared.b16 {%0,%1,%2,%3}, [%4];"
                 : "=r"(r[0]), "=r"(r[1]), "=r"(r[2]), "=r"(r[3]) : "r"(addr));
}
__device__ __forceinline__ void mma_bf16(float* c, const uint32_t* a, const uint32_t* b) {
    asm volatile(
        "mma.sync.aligned.m16n8k16.row.col.f32.bf16.bf16.f32 "
        "{%0,%1,%2,%3}, {%4,%5,%6,%7}, {%8,%9}, {%0,%1,%2,%3};"
        : "+f"(c[0]), "+f"(c[1]), "+f"(c[2]), "+f"(c[3])
        : "r"(a[0]), "r"(a[1]), "r"(a[2]), "r"(a[3]), "r"(b[0]), "r"(b[1]));
}
__device__ __forceinline__ void mma_f16(float* c, const uint32_t* a, const uint32_t* b) {
    asm volatile(
        "mma.sync.aligned.m16n8k16.row.col.f32.f16.f16.f32 "
        "{%0,%1,%2,%3}, {%4,%5,%6,%7}, {%8,%9}, {%0,%1,%2,%3};"
        : "+f"(c[0]), "+f"(c[1]), "+f"(c[2]), "+f"(c[3])
        : "r"(a[0]), "r"(a[1]), "r"(a[2]), "r"(a[3]), "r"(b[0]), "r"(b[1]));
}

__device__ __forceinline__ void split2(float x, float y, uint32_t& hi, uint32_t& lo) {
    __nv_bfloat162 h = __floats2bfloat162_rn(x, y);
    hi = *(uint32_t*)&h;
    __nv_bfloat162 l = __floats2bfloat162_rn(x - __bfloat162float(h.x),
                                             y - __bfloat162float(h.y));
    lo = *(uint32_t*)&l;
}
__device__ __forceinline__ void split2h(float x, float y, uint32_t& hi, uint32_t& lo) {
    __half hx = __float2half_rn(x), hy = __float2half_rn(y);
    __half2 hh = __halves2half2(hx, hy);
    hi = *(uint32_t*)&hh;
    __half lx = __float2half_rn(x - __half2float(hx));
    __half ly = __float2half_rn(y - __half2float(hy));
    __half2 ll = __halves2half2(lx, ly);
    lo = *(uint32_t*)&ll;
}

// GEMM smem tile: [128 rows][40 elems] = 80 B/row, 10240 B/array
#define TROW 80
#define TBYTES 10240
#define STAGE (3 * TBYTES)   // Ah, Al, B per stage = 30720; 3 stages = 92160

// Attention smem row: 64 bf16 padded to 72 = 144 B
#define ATRB 144
#define AKV (64 * ATRB)

// ---------------- fused converts: x split + w_in + w_out (one launch) ----------------
#define N4X  (MROWS * GK / 4)                 // 1572864
#define N4WI (3 * DMODEL * GK / 4)            // 442368
#define N4WO (DMODEL * GK / 4)                // 147456
__global__ __launch_bounds__(256) void convert_all_kernel(
    const float* __restrict__ x, __half* __restrict__ xh, __half* __restrict__ xl,
    const float* __restrict__ wi, __half* __restrict__ wih,
    const float* __restrict__ wo, __half* __restrict__ woh)
{
    int i = blockIdx.x * blockDim.x + threadIdx.x;
    if (i < N4X) {
        float4 v = ((const float4*)x)[i];
        uint32_t h0, l0, h1, l1;
        split2h(v.x, v.y, h0, l0);
        split2h(v.z, v.w, h1, l1);
        ((uint32_t*)xh)[2 * i] = h0; ((uint32_t*)xh)[2 * i + 1] = h1;
        ((uint32_t*)xl)[2 * i] = l0; ((uint32_t*)xl)[2 * i + 1] = l1;
    } else if (i < N4X + N4WI) {
        int j = i - N4X;
        float4 v = ((const float4*)wi)[j];
        __half2* O = (__half2*)wih;
        O[2 * j]     = __floats2half2_rn(v.x, v.y);
        O[2 * j + 1] = __floats2half2_rn(v.z, v.w);
    } else if (i < N4X + N4WI + N4WO) {
        int j = i - N4X - N4WI;
        float4 v = ((const float4*)wo)[j];
        __half2* O = (__half2*)woh;
        O[2 * j]     = __floats2half2_rn(v.x, v.y);
        O[2 * j + 1] = __floats2half2_rn(v.z, v.w);
    }
}

// ----------------------------------------------------------------------------
// 2-term fp16 mma.sync GEMM. R17: warp layout 4m x 2n (warp tile 32x64) —
// per 32-k chunk LDSM.x4 drops 20 -> 16 (A:8, B:8) at identical MMA count
// and accumulator footprint. 3-stage cp.async ring, one barrier per chunk.
// ----------------------------------------------------------------------------
__global__ __launch_bounds__(256, 2) void mma_gemm_kernel(
    const __half* __restrict__ Ah_, const __half* __restrict__ Al_,
    const __half* __restrict__ B_,
    const float* __restrict__ bias, float* __restrict__ C,
    __nv_bfloat16* __restrict__ Ch, __nv_bfloat16* __restrict__ Cl,
    size_t region_stride)
{
    extern __shared__ char smem[];
    const uint32_t sb = smem_u32(smem);
    const int tid = threadIdx.x;
    const int wid = tid >> 5;
    const int lane = tid & 31;
    const int wm = wid & 3;          // 4 m-warps -> 32 rows each
    const int wn = wid >> 2;         // 2 n-warps -> 64 cols each
    const int row0 = blockIdx.y * 128;
    const int col0 = blockIdx.x * 128;

    const char* gA_h = (const char*)(Ah_ + (size_t)row0 * GK);
    const char* gA_l = (const char*)(Al_ + (size_t)row0 * GK);
    const char* gB   = (const char*)(B_  + (size_t)col0 * GK);

    const int r0g = (tid + 0)   >> 2, g0 = (tid + 0)   & 3;
    const int r1g = (tid + 256) >> 2, g1 = (tid + 256) & 3;

#define LOAD_CHUNK(kc, stage) do {                                          \
        const uint32_t s0_ = sb + (stage) * STAGE;                          \
        {                                                                   \
            uint32_t d = (uint32_t)r0g * TROW + g0 * 16;                    \
            size_t src = (size_t)r0g * (GK * 2) + (size_t)(kc) * 64 + g0 * 16; \
            CP_ASYNC16(s0_ + 0 * TBYTES + d, gA_h + src);                   \
            CP_ASYNC16(s0_ + 1 * TBYTES + d, gA_l + src);                   \
            CP_ASYNC16(s0_ + 2 * TBYTES + d, gB + src);                     \
        }                                                                   \
        {                                                                   \
            uint32_t d = (uint32_t)r1g * TROW + g1 * 16;                    \
            size_t src = (size_t)r1g * (GK * 2) + (size_t)(kc) * 64 + g1 * 16; \
            CP_ASYNC16(s0_ + 0 * TBYTES + d, gA_h + src);                   \
            CP_ASYNC16(s0_ + 1 * TBYTES + d, gA_l + src);                   \
            CP_ASYNC16(s0_ + 2 * TBYTES + d, gB + src);                     \
        }                                                                   \
        CP_COMMIT();                                                        \
    } while (0)

    float acc[2][8][4];
#pragma unroll
    for (int im = 0; im < 2; im++)
#pragma unroll
        for (int jn = 0; jn < 8; jn++)
#pragma unroll
            for (int q = 0; q < 4; q++) acc[im][jn][q] = 0.0f;

    // A x4: row = wm*32 + im*16 + (lane&7) + ((lane>>3)&1)*8, k-half = lane>>4
    const uint32_t aoff = (uint32_t)(wm * 32 + (lane & 7) + ((lane >> 3) & 1) * 8) * TROW
                        + (uint32_t)(lane >> 4) * 16;
    // B x4 merged (pair p covers jn=2p,2p+1):
    // row = wn*64 + p*16 + (lane&7) + ((lane>>4)&1)*8, k-half = (lane>>3)&1
    const uint32_t boff4 = (uint32_t)(wn * 64 + (lane & 7) + ((lane >> 4) & 1) * 8) * TROW
                         + (uint32_t)((lane >> 3) & 1) * 16;

    LOAD_CHUNK(0, 0);
    LOAD_CHUNK(1, 1);
    const int NKC = GK / 32;  // 24
    int stage = 0, wstage = 2;
    for (int kc = 0; kc < NKC; kc++) {
        if (kc + 2 < NKC) CP_WAIT1();
        else              CP_WAIT0();
        __syncthreads();
        if (kc + 2 < NKC) LOAD_CHUNK(kc + 2, wstage);

        const uint32_t s0 = sb + stage * STAGE;
        // preload ALL B fragments for the chunk: 4 pairs x 2 k16 halves
        uint32_t bfr0[4][4], bfr1[4][4];
#pragma unroll
        for (int p = 0; p < 4; p++) {
            ldmx4(bfr0[p], s0 + 2 * TBYTES + boff4 + (uint32_t)p * 16 * TROW);
            ldmx4(bfr1[p], s0 + 2 * TBYTES + boff4 + (uint32_t)p * 16 * TROW + 32);
        }
#pragma unroll
        for (int im = 0; im < 2; im++) {
            uint32_t ah0[4], al0[4], ah1[4], al1[4];
            const uint32_t abase = aoff + (uint32_t)im * 16 * TROW;
            ldmx4(ah0, s0 + 0 * TBYTES + abase);
            ldmx4(al0, s0 + 1 * TBYTES + abase);
            ldmx4(ah1, s0 + 0 * TBYTES + abase + 32);
            ldmx4(al1, s0 + 1 * TBYTES + abase + 32);
#pragma unroll
            for (int jn = 0; jn < 8; jn++) {
                const uint32_t* b0 = &bfr0[jn >> 1][(jn & 1) * 2];
                const uint32_t* b1 = &bfr1[jn >> 1][(jn & 1) * 2];
                mma_f16(acc[im][jn], ah0, b0);
                mma_f16(acc[im][jn], al0, b0);
                mma_f16(acc[im][jn], ah1, b1);
                mma_f16(acc[im][jn], al1, b1);
            }
        }
        stage = (stage == 2) ? 0 : stage + 1;
        wstage = (wstage == 2) ? 0 : wstage + 1;
    }

    const int gid = lane >> 2, tq = lane & 3;
#pragma unroll
    for (int jn = 0; jn < 8; jn++) {
        const int colg = col0 + wn * 64 + jn * 8 + tq * 2;
        const int region = colg / DMODEL;
        const int cc = colg - region * DMODEL;
        float* Cb = C + (size_t)region * region_stride + cc;
        __nv_bfloat16* Chb = Ch ? Ch + (size_t)region * region_stride + cc : nullptr;
        __nv_bfloat16* Clb = Ch ? Cl + (size_t)region * region_stride + cc : nullptr;
        const float bx = bias[colg], by = bias[colg + 1];
#pragma unroll
        for (int im = 0; im < 2; im++) {
            const int rg = row0 + wm * 32 + im * 16 + gid;
            float2 v0, v1;
            v0.x = acc[im][jn][0] + bx; v0.y = acc[im][jn][1] + by;
            v1.x = acc[im][jn][2] + bx; v1.y = acc[im][jn][3] + by;
            *(float2*)(Cb + (size_t)rg * DMODEL) = v0;
            *(float2*)(Cb + (size_t)(rg + 8) * DMODEL) = v1;
            if (Chb) {
                uint32_t h0, l0, h1, l1;
                split2(v0.x, v0.y, h0, l0);
                split2(v1.x, v1.y, h1, l1);
                *(uint32_t*)(Chb + (size_t)rg * DMODEL) = h0;
                *(uint32_t*)(Clb + (size_t)rg * DMODEL) = l0;
                *(uint32_t*)(Chb + (size_t)(rg + 8) * DMODEL) = h1;
                *(uint32_t*)(Clb + (size_t)(rg + 8) * DMODEL) = l1;
            }
        }
    }
#undef LOAD_CHUNK
}

// ----------------------------------------------------------------------------
// mma.sync flash attention (R16 core, unchanged numerics).
// ----------------------------------------------------------------------------
__global__ __launch_bounds__(256, 2) void attn_mma_kernel(
    const __nv_bfloat16* __restrict__ qkvh, const __nv_bfloat16* __restrict__ qkvl,
    __half* __restrict__ mixh, __half* __restrict__ mixl)
{
    extern __shared__ char smc[];
    const uint32_t sb = smem_u32(smc);
    const uint32_t sQh = sb;
    const uint32_t sQl = sQh + 128 * ATRB;
    const uint32_t sKV = sQl + 128 * ATRB;

    const int tid = threadIdx.x;
    const int wid = tid >> 5;
    const int lane = tid & 31;
    const int bh = blockIdx.y;
    const int b = bh / NHEAD;
    const int h = bh - b * NHEAD;
    const int q0 = blockIdx.x * 128;

    const char* gqh = (const char*)qkvh;
    const char* gql = (const char*)qkvl;
    const char* gkh = (const char*)(qkvh + SBD);
    const char* gkl = (const char*)(qkvl + SBD);
    const char* gvh = (const char*)(qkvh + 2 * SBD);
    const char* gvl = (const char*)(qkvl + 2 * SBD);

    const int gr = tid >> 3;
    const int gg = (tid & 7) * 16;

#pragma unroll
    for (int i = 0; i < 4; i++) {
        const int r = gr + i * 32;
        const size_t off = (((size_t)(q0 + r) * BATCH + b) * DMODEL + h * HDIM) * 2 + gg;
        CP_ASYNC16(sQh + r * ATRB + gg, gqh + off);
        CP_ASYNC16(sQl + r * ATRB + gg, gql + off);
    }
#pragma unroll
    for (int i = 0; i < 2; i++) {
        const int r = gr + i * 32;
        const size_t off = (((size_t)r * BATCH + b) * DMODEL + h * HDIM) * 2 + gg;
        CP_ASYNC16(sKV + 0 * AKV + r * ATRB + gg, gkh + off);
        CP_ASYNC16(sKV + 1 * AKV + r * ATRB + gg, gkl + off);
        CP_ASYNC16(sKV + 2 * AKV + r * ATRB + gg, gvh + off);
        CP_ASYNC16(sKV + 3 * AKV + r * ATRB + gg, gvl + off);
    }
    CP_COMMIT();

    const uint32_t qoff = (uint32_t)(wid * 16 + (lane & 7) + ((lane >> 3) & 1) * 8) * ATRB
                        + (uint32_t)(lane >> 4) * 16;
    const uint32_t koff = (uint32_t)((lane & 7) + ((lane >> 4) & 1) * 8) * ATRB
                        + (uint32_t)((lane >> 3) & 1) * 16;
    const uint32_t voff = (uint32_t)((lane & 7) + ((lane >> 3) & 1) * 8) * ATRB
                        + (uint32_t)((lane >> 4) & 1) * 16;

    const int qrA = q0 + wid * 16 + (lane >> 2);
    const int qrB = qrA + 8;
    const bool qmA = (qrA == 0) || (qrA >= TOKENS);
    const bool qmB = (qrB == 0) || (qrB >= TOKENS);
    const int ncol = (lane & 3) * 2;

    float mA = -1e30f, mB = -1e30f, lsumA = 0.0f, lsumB = 0.0f;
    float o[8][4];
#pragma unroll
    for (int j = 0; j < 8; j++)
#pragma unroll
        for (int q = 0; q < 4; q++) o[j][q] = 0.0f;

    CP_WAIT0();
    __syncthreads();

    for (int kt = 0; kt < S_LEN; kt += 64) {
        const uint32_t sK = sKV + (((kt >> 6) & 1) ? 4 * AKV : 0);
        if (kt + 64 < S_LEN) {
            const uint32_t sN = sKV + (((kt >> 6) & 1) ? 0 : 4 * AKV);
#pragma unroll
            for (int i = 0; i < 2; i++) {
                const int r = gr + i * 32;
                const size_t off =
                    (((size_t)(kt + 64 + r) * BATCH + b) * DMODEL + h * HDIM) * 2 + gg;
                CP_ASYNC16(sN + 0 * AKV + r * ATRB + gg, gkh + off);
                CP_ASYNC16(sN + 1 * AKV + r * ATRB + gg, gkl + off);
                CP_ASYNC16(sN + 2 * AKV + r * ATRB + gg, gvh + off);
                CP_ASYNC16(sN + 3 * AKV + r * ATRB + gg, gvl + off);
            }
            CP_COMMIT();
        }

        float s[8][4];
#pragma unroll
        for (int j = 0; j < 8; j++)
#pragma unroll
            for (int q = 0; q < 4; q++) s[j][q] = 0.0f;

#pragma unroll
        for (int kc = 0; kc < 4; kc++) {
            uint32_t q_h[4], q_l[4];
            ldmx4(q_h, sQh + qoff + kc * 32);
            ldmx4(q_l, sQl + qoff + kc * 32);
#pragma unroll
            for (int np = 0; np < 4; np++) {
                uint32_t k_h[4], k_l[4];
                ldmx4(k_h, sK + 0 * AKV + koff + np * 16 * ATRB + kc * 32);
                ldmx4(k_l, sK + 1 * AKV + koff + np * 16 * ATRB + kc * 32);
                mma_bf16(s[2 * np],     q_h, k_h + 0);
                mma_bf16(s[2 * np],     q_h, k_l + 0);
                mma_bf16(s[2 * np],     q_l, k_h + 0);
                mma_bf16(s[2 * np + 1], q_h, k_h + 2);
                mma_bf16(s[2 * np + 1], q_h, k_l + 2);
                mma_bf16(s[2 * np + 1], q_l, k_h + 2);
            }
        }

        float vmA = -1e30f, vmB = -1e30f;
        if (kt + 64 >= S_LEN) {
#pragma unroll
            for (int j = 0; j < 8; j++) {
                const int n0 = kt + j * 8 + ncol;
                const bool k0m = n0 >= TOKENS, k1m = (n0 + 1) >= TOKENS;
                float t0 = s[j][0] * SSCALE; if (k0m && qmA) t0 = MASKVAL;
                float t1 = s[j][1] * SSCALE; if (k1m && qmA) t1 = MASKVAL;
                float t2 = s[j][2] * SSCALE; if (k0m && qmB) t2 = MASKVAL;
                float t3 = s[j][3] * SSCALE; if (k1m && qmB) t3 = MASKVAL;
                s[j][0] = t0; s[j][1] = t1; s[j][2] = t2; s[j][3] = t3;
                vmA = fmaxf(vmA, fmaxf(t0, t1));
                vmB = fmaxf(vmB, fmaxf(t2, t3));
            }
        } else {
#pragma unroll
            for (int j = 0; j < 8; j++) {
                float t0 = s[j][0] * SSCALE;
                float t1 = s[j][1] * SSCALE;
                float t2 = s[j][2] * SSCALE;
                float t3 = s[j][3] * SSCALE;
                s[j][0] = t0; s[j][1] = t1; s[j][2] = t2; s[j][3] = t3;
                vmA = fmaxf(vmA, fmaxf(t0, t1));
                vmB = fmaxf(vmB, fmaxf(t2, t3));
            }
        }
        vmA = fmaxf(vmA, __shfl_xor_sync(0xffffffffu, vmA, 1));
        vmA = fmaxf(vmA, __shfl_xor_sync(0xffffffffu, vmA, 2));
        vmB = fmaxf(vmB, __shfl_xor_sync(0xffffffffu, vmB, 1));
        vmB = fmaxf(vmB, __shfl_xor_sync(0xffffffffu, vmB, 2));

        const float nmA = fmaxf(mA, vmA), fA = exp2f(mA - nmA);
        const float nmB = fmaxf(mB, vmB), fB = exp2f(mB - nmB);
        mA = nmA; mB = nmB;
        lsumA *= fA; lsumB *= fB;

        float psA = 0.0f, psB = 0.0f;
#pragma unroll
        for (int j = 0; j < 8; j++) {
            float p0 = exp2f(s[j][0] - mA), p1 = exp2f(s[j][1] - mA);
            float p2 = exp2f(s[j][2] - mB), p3 = exp2f(s[j][3] - mB);
            s[j][0] = p0; s[j][1] = p1; s[j][2] = p2; s[j][3] = p3;
            psA += p0 + p1; psB += p2 + p3;
            o[j][0] *= fA; o[j][1] *= fA; o[j][2] *= fB; o[j][3] *= fB;
        }
        psA += __shfl_xor_sync(0xffffffffu, psA, 1);
        psA += __shfl_xor_sync(0xffffffffu, psA, 2);
        psB += __shfl_xor_sync(0xffffffffu, psB, 1);
        psB += __shfl_xor_sync(0xffffffffu, psB, 2);
        lsumA += psA; lsumB += psB;

#pragma unroll
        for (int kc = 0; kc < 4; kc++) {
            const int j0 = 2 * kc, j1 = 2 * kc + 1;
            uint32_t a_h[4], a_l[4];
            split2(s[j0][0], s[j0][1], a_h[0], a_l[0]);
            split2(s[j0][2], s[j0][3], a_h[1], a_l[1]);
            split2(s[j1][0], s[j1][1], a_h[2], a_l[2]);
            split2(s[j1][2], s[j1][3], a_h[3], a_l[3]);
#pragma unroll
            for (int np = 0; np < 4; np++) {
                uint32_t v_h[4], v_l[4];
                ldmx4t(v_h, sK + 2 * AKV + voff + kc * 16 * ATRB + np * 32);
                ldmx4t(v_l, sK + 3 * AKV + voff + kc * 16 * ATRB + np * 32);
                mma_bf16(o[2 * np],     a_h, v_h + 0);
                mma_bf16(o[2 * np],     a_h, v_l + 0);
                mma_bf16(o[2 * np],     a_l, v_h + 0);
                mma_bf16(o[2 * np + 1], a_h, v_h + 2);
                mma_bf16(o[2 * np + 1], a_h, v_l + 2);
                mma_bf16(o[2 * np + 1], a_l, v_h + 2);
            }
        }

        CP_WAIT0();
        __syncthreads();
    }

    const float invA = 1.0f / lsumA, invB = 1.0f / lsumB;
    const size_t baseA = ((size_t)qrA * BATCH + b) * DMODEL + h * HDIM + ncol;
    const size_t baseB = ((size_t)qrB * BATCH + b) * DMODEL + h * HDIM + ncol;
#pragma unroll
    for (int j = 0; j < 8; j++) {
        uint32_t h0, l0, h1, l1;
        split2h(o[j][0] * invA, o[j][1] * invA, h0, l0);
        split2h(o[j][2] * invB, o[j][3] * invB, h1, l1);
        *(uint32_t*)(mixh + baseA + j * 8) = h0;
        *(uint32_t*)(mixl + baseA + j * 8) = l0;
        *(uint32_t*)(mixh + baseB + j * 8) = h1;
        *(uint32_t*)(mixl + baseB + j * 8) = l1;
    }
}

extern "C" void kernel_launch(void* const* d_in, const int* in_sizes, int n_in,
                              void* d_out, int out_size)
{
    const float* x      = (const float*)d_in[0];
    const float* w_in   = (const float*)d_in[1];
    const float* b_in   = (const float*)d_in[2];
    const float* w_out  = (const float*)d_in[3];
    const float* b_out  = (const float*)d_in[4];
    float* out = (float*)d_out;

    float* q_out = out;
    float* o_out = out + 3 * SBD;

    __half *xh, *xl, *wih, *woh, *mixh, *mixl;
    __nv_bfloat16 *qkvh, *qkvl;
    cudaGetSymbolAddress((void**)&xh,   g_xh);
    cudaGetSymbolAddress((void**)&xl,   g_xl);
    cudaGetSymbolAddress((void**)&wih,  g_wih);
    cudaGetSymbolAddress((void**)&woh,  g_woh);
    cudaGetSymbolAddress((void**)&mixh, g_mixh);
    cudaGetSymbolAddress((void**)&mixl, g_mixl);
    cudaGetSymbolAddress((void**)&qkvh, g_qkvh);
    cudaGetSymbolAddress((void**)&qkvl, g_qkvl);

    const int gemm_smem = 3 * STAGE;                 // 92160
    const int attn_smem = 2 * 128 * ATRB + 8 * AKV;  // 110592
    cudaFuncSetAttribute(mma_gemm_kernel, cudaFuncAttributeMaxDynamicSharedMemorySize, gemm_smem);
    cudaFuncSetAttribute(attn_mma_kernel, cudaFuncAttributeMaxDynamicSharedMemorySize, attn_smem);

    // 0) all converts in one launch
    {
        const int total = N4X + N4WI + N4WO;
        convert_all_kernel<<<(total + 255) / 256, 256>>>(x, xh, xl, w_in, wih, w_out, woh);
    }

    // 1) QKV projection -> fp32 q/k/v in d_out + bf16 hi/lo for attention
    {
        dim3 grid(3 * DMODEL / 128, MROWS / 128);
        mma_gemm_kernel<<<grid, 256, gemm_smem>>>(xh, xl, wih, b_in, q_out,
                                                  qkvh, qkvl, SBD);
    }

    // 2) tensor-core flash attention
    {
        dim3 grid(S_LEN / 128, BATCH * NHEAD);
        attn_mma_kernel<<<grid, 256, attn_smem>>>(qkvh, qkvl, mixh, mixl);
    }

    // 3) output projection
    {
        dim3 grid(DMODEL / 128, MROWS / 128);
        mma_gemm_kernel<<<grid, 256, gemm_smem>>>(mixh, mixl, woh, b_out, o_out,
                                                  nullptr, nullptr, 0);
    }
}